// round 10
// baseline (speedup 1.0000x reference)
#include <cuda_runtime.h>
#include <cuda_bf16.h>
#include <mma.h>
#include <math.h>

using namespace nvcuda;
typedef __nv_bfloat16 bf16;

#define Ss 256
#define Bb 64
#define Ii 1024
#define Hh 1024
#define H3 3072
#define Pp 1024
#define Ll 256
#define SCAN_BLOCKS 128

__device__ float g_GI[(size_t)Ss * Bb * H3];
__device__ bf16 g_inch[(size_t)Ss * Bb * Ii], g_incl[(size_t)Ss * Bb * Ii];
__device__ bf16 g_Wih_h[(size_t)H3 * Ii],  g_Wih_l[(size_t)H3 * Ii];
__device__ bf16 g_Whh_h[(size_t)H3 * Hh],  g_Whh_l[(size_t)H3 * Hh];
__device__ bf16 g_Wq_h [(size_t)Pp * Hh],  g_Wq_l [(size_t)Pp * Hh];
__device__ bf16 g_Qh[(size_t)Ss * Bb * Pp], g_Ql[(size_t)Ss * Bb * Pp];
__device__ bf16 g_ph[(size_t)Ll * Bb * Pp], g_pl[(size_t)Ll * Bb * Pp];
__device__ bf16 g_ah[(size_t)Bb * Ss * Ll], g_al[(size_t)Bb * Ss * Ll];
__device__ bf16 g_ch_h[2][Bb * Hh], g_ch_l[2][Bb * Hh];
__device__ bf16 g_hsh[(size_t)Ss * Bb * Hh], g_hsl[(size_t)Ss * Bb * Hh];
__device__ unsigned g_count;

__device__ __forceinline__ void cpasync16(void* dst, const void* src) {
    unsigned d = (unsigned)__cvta_generic_to_shared(dst);
    asm volatile("cp.async.cg.shared.global [%0], [%1], 16;\n" :: "r"(d), "l"(src));
}
__device__ __forceinline__ void cpcommit() { asm volatile("cp.async.commit_group;\n"); }
template<int N> __device__ __forceinline__ void cpwait() {
    asm volatile("cp.async.wait_group %0;\n" :: "n"(N));
}

__global__ void split_kernel(const float* __restrict__ x,
                             bf16* __restrict__ hi, bf16* __restrict__ lo, int n)
{
    int i = blockIdx.x * blockDim.x + threadIdx.x;
    if (i < n) {
        float v = x[i];
        bf16 h = __float2bfloat16(v);
        hi[i] = h;
        lo[i] = __float2bfloat16(v - __bfloat162float(h));
    }
}

// ------- split-bf16 NT GEMM, 4-stage cp.async pipeline (race-free) --------
// 128x128 tile, BK=32, 256 thr / 8 warps, warp tile 64x32.
// Stage layout: 4 bufs (Ah,Al,Bh,Bl) of 128x40 bf16 each; 4 stages.
__global__ void __launch_bounds__(256)
wmma_split_nt(const bf16* __restrict__ Ah, const bf16* __restrict__ Al,
              long ldaR, long batchA,
              const bf16* __restrict__ Bh, const bf16* __restrict__ Bl,
              long ldbR, long batchB,
              float* __restrict__ C, long ldcR, long cstr, long batchC,
              const float* __restrict__ bias,
              bf16* __restrict__ Ch, bf16* __restrict__ Cl,
              int K)
{
    extern __shared__ bf16 sm[];
    const int LD = 40;
    const int STG = 4 * 128 * LD;              // bf16 per stage = 20480
    int z = blockIdx.z;
    Ah += (size_t)z * batchA;  Al += (size_t)z * batchA;
    Bh += (size_t)z * batchB;  Bl += (size_t)z * batchB;
    if (C) C += (size_t)z * batchC;
    int m0 = blockIdx.x * 128, n0 = blockIdx.y * 128;
    int tid = threadIdx.x;
    int w = tid >> 5, wr = w >> 2, wc = w & 3;

    wmma::fragment<wmma::accumulator,16,16,16,float> acc[4][2];
#pragma unroll
    for (int i = 0; i < 4; i++)
#pragma unroll
        for (int j = 0; j < 2; j++) wmma::fill_fragment(acc[i][j], 0.f);

    auto issue = [&](int kt) {
        bf16* base = sm + (size_t)(kt & 3) * STG;
        int k0 = kt * 32;
#pragma unroll
        for (int i = 0; i < 8; i++) {
            int id = tid + 256 * i;            // 0..2047
            int buf = id >> 9;                 // 0:Ah 1:Al 2:Bh 3:Bl
            int e = id & 511;
            int r = e >> 2, c = (e & 3) * 8;
            const bf16* src;
            if      (buf == 0) src = Ah + (size_t)(m0 + r) * ldaR + k0 + c;
            else if (buf == 1) src = Al + (size_t)(m0 + r) * ldaR + k0 + c;
            else if (buf == 2) src = Bh + (size_t)(n0 + r) * ldbR + k0 + c;
            else               src = Bl + (size_t)(n0 + r) * ldbR + k0 + c;
            cpasync16(base + (size_t)buf * 128 * LD + r * LD + c, src);
        }
        cpcommit();
    };

    int KT = K / 32;
    issue(0); if (KT > 1) issue(1); if (KT > 2) issue(2);
    for (int kt = 0; kt < KT; kt++) {
        if      (kt < KT - 2) cpwait<2>();
        else if (kt == KT - 2) cpwait<1>();
        else                   cpwait<0>();
        __syncthreads();
        if (kt + 3 < KT) issue(kt + 3);        // after sync: mma(kt-1) done everywhere
        bf16* base = sm + (size_t)(kt & 3) * STG;
        bf16 *sAh_ = base, *sAl_ = base + 128*LD, *sBh_ = base + 2*128*LD, *sBl_ = base + 3*128*LD;
#pragma unroll
        for (int ks = 0; ks < 2; ks++) {
            wmma::fragment<wmma::matrix_a,16,16,16,bf16,wmma::row_major> ah[4], al[4];
            wmma::fragment<wmma::matrix_b,16,16,16,bf16,wmma::col_major> bh[2], bl[2];
#pragma unroll
            for (int i = 0; i < 4; i++) {
                wmma::load_matrix_sync(ah[i], sAh_ + (wr*64 + i*16)*LD + ks*16, LD);
                wmma::load_matrix_sync(al[i], sAl_ + (wr*64 + i*16)*LD + ks*16, LD);
            }
#pragma unroll
            for (int j = 0; j < 2; j++) {
                wmma::load_matrix_sync(bh[j], sBh_ + (wc*32 + j*16)*LD + ks*16, LD);
                wmma::load_matrix_sync(bl[j], sBl_ + (wc*32 + j*16)*LD + ks*16, LD);
            }
#pragma unroll
            for (int i = 0; i < 4; i++)
#pragma unroll
                for (int j = 0; j < 2; j++) {
                    wmma::mma_sync(acc[i][j], ah[i], bh[j], acc[i][j]);
                    wmma::mma_sync(acc[i][j], ah[i], bl[j], acc[i][j]);
                    wmma::mma_sync(acc[i][j], al[i], bh[j], acc[i][j]);
                }
        }
    }
    __syncthreads();

    if (Ch) {
        float* smf = (float*)sm;
#pragma unroll
        for (int i = 0; i < 4; i++)
#pragma unroll
            for (int j = 0; j < 2; j++)
                wmma::store_matrix_sync(smf + (wr*64 + i*16)*128 + wc*32 + j*16,
                                        acc[i][j], 128, wmma::mem_row_major);
        __syncthreads();
        for (int e = tid; e < 16384; e += 256) {
            int m = e >> 7, n = e & 127;
            float v = smf[e] + (bias ? bias[n0 + n] : 0.f);
            bf16 hi = __float2bfloat16(v);
            size_t off = (size_t)(m0 + m) * ldcR + n0 + n;
            Ch[off] = hi;
            Cl[off] = __float2bfloat16(v - __bfloat162float(hi));
        }
    } else if (cstr == 1) {
#pragma unroll
        for (int i = 0; i < 4; i++)
#pragma unroll
            for (int j = 0; j < 2; j++)
                wmma::store_matrix_sync(
                    C + (size_t)(m0 + wr*64 + i*16) * ldcR + n0 + wc*32 + j*16,
                    acc[i][j], ldcR, wmma::mem_row_major);
    } else {
        float* smf = (float*)sm;
#pragma unroll
        for (int i = 0; i < 4; i++)
#pragma unroll
            for (int j = 0; j < 2; j++)
                wmma::store_matrix_sync(smf + (wr*64 + i*16)*128 + wc*32 + j*16,
                                        acc[i][j], 128, wmma::mem_row_major);
        __syncthreads();
        for (int e = tid; e < 16384; e += 256) {
            int m = e >> 7, n = e & 127;
            C[(size_t)(m0 + m) * ldcR + (size_t)(n0 + n) * cstr] = smf[e];
        }
    }
}

// -------- wmma NN GEMM (context) — unchanged --------
__global__ void __launch_bounds__(256)
wmma_split_nn(const bf16* __restrict__ Ah, const bf16* __restrict__ Al,
              long ldaR, long batchA,
              const bf16* __restrict__ Bh, const bf16* __restrict__ Bl,
              long ldbR, long batchB,
              float* __restrict__ C, long ldcR, long batchC, int K)
{
    extern __shared__ bf16 sm[];
    const int ALD = 40, BLD = 136;
    const int STG = 2*128*ALD + 2*32*BLD;
    int z = blockIdx.z;
    Ah += (size_t)z * batchA;  Al += (size_t)z * batchA;
    Bh += (size_t)z * batchB;  Bl += (size_t)z * batchB;
    C  += (size_t)z * batchC;
    int m0 = blockIdx.x * 128, n0 = blockIdx.y * 128;
    int tid = threadIdx.x;
    int w = tid >> 5, wr = w >> 2, wc = w & 3;

    wmma::fragment<wmma::accumulator,16,16,16,float> acc[4][2];
#pragma unroll
    for (int i = 0; i < 4; i++)
#pragma unroll
        for (int j = 0; j < 2; j++) wmma::fill_fragment(acc[i][j], 0.f);

    auto issue = [&](int kt, int stg) {
        bf16* base = sm + (size_t)stg * STG;
        bf16 *dAh = base, *dAl = base + 128*ALD, *dBh = base + 2*128*ALD, *dBl = base + 2*128*ALD + 32*BLD;
        int k0 = kt * 32;
#pragma unroll
        for (int i = 0; i < 8; i++) {
            int id = tid + 256 * i;
            int buf = id >> 9;
            int e = id & 511;
            if (buf < 2) {
                int r = e >> 2, c = (e & 3) * 8;
                const bf16* src = (buf ? Al : Ah) + (size_t)(m0 + r) * ldaR + k0 + c;
                cpasync16((buf ? dAl : dAh) + r * ALD + c, src);
            } else {
                int r = e >> 4, c = (e & 15) * 8;
                const bf16* src = (buf == 3 ? Bl : Bh) + (size_t)(k0 + r) * ldbR + n0 + c;
                cpasync16((buf == 3 ? dBl : dBh) + r * BLD + c, src);
            }
        }
        cpcommit();
    };

    int KT = K / 32;
    issue(0, 0);
    for (int kt = 0; kt < KT; kt++) {
        if (kt + 1 < KT) { issue(kt + 1, (kt + 1) & 1); cpwait<1>(); }
        else             { cpwait<0>(); }
        __syncthreads();
        bf16* base = sm + (size_t)(kt & 1) * STG;
        bf16 *sAh_ = base, *sAl_ = base + 128*ALD, *sBh_ = base + 2*128*ALD, *sBl_ = sBh_ + 32*BLD;
#pragma unroll
        for (int ks = 0; ks < 2; ks++) {
            wmma::fragment<wmma::matrix_a,16,16,16,bf16,wmma::row_major> ah[4], al[4];
            wmma::fragment<wmma::matrix_b,16,16,16,bf16,wmma::row_major> bh[2], bl[2];
#pragma unroll
            for (int i = 0; i < 4; i++) {
                wmma::load_matrix_sync(ah[i], sAh_ + (wr*64 + i*16)*ALD + ks*16, ALD);
                wmma::load_matrix_sync(al[i], sAl_ + (wr*64 + i*16)*ALD + ks*16, ALD);
            }
#pragma unroll
            for (int j = 0; j < 2; j++) {
                wmma::load_matrix_sync(bh[j], sBh_ + (ks*16)*BLD + wc*32 + j*16, BLD);
                wmma::load_matrix_sync(bl[j], sBl_ + (ks*16)*BLD + wc*32 + j*16, BLD);
            }
#pragma unroll
            for (int i = 0; i < 4; i++)
#pragma unroll
                for (int j = 0; j < 2; j++) {
                    wmma::mma_sync(acc[i][j], ah[i], bh[j], acc[i][j]);
                    wmma::mma_sync(acc[i][j], ah[i], bl[j], acc[i][j]);
                    wmma::mma_sync(acc[i][j], al[i], bh[j], acc[i][j]);
                }
        }
        __syncthreads();
    }
#pragma unroll
    for (int i = 0; i < 4; i++)
#pragma unroll
        for (int j = 0; j < 2; j++)
            wmma::store_matrix_sync(
                C + (size_t)(m0 + wr*64 + i*16) * ldcR + n0 + wc*32 + j*16,
                acc[i][j], ldcR, wmma::mem_row_major);
}

// -------- persistent wmma GRU scan — unchanged (proven) --------
__global__ void __launch_bounds__(256)
gru_scan(const float* __restrict__ bih, const float* __restrict__ bhh,
         const int* __restrict__ length, const float* __restrict__ h_init,
         float* __restrict__ hs)
{
    extern __shared__ bf16 ssm[];
    const int WLD = 1032, ALD = 72;
    const int ASTG = 2 * 64 * ALD;
    bf16* sWh = ssm;
    bf16* sWl = sWh + 32 * WLD;
    bf16* sA  = sWl + 32 * WLD;
    float* ghsm = (float*)sA;

    int tid = threadIdx.x;
    int w = tid >> 5, wr = w & 3, wc = w >> 2;
    int j0 = blockIdx.x * 8;

    for (int i = tid; i < 32 * WLD; i += 256) {
        sWh[i] = __float2bfloat16(0.f);
        sWl[i] = __float2bfloat16(0.f);
    }
    __syncthreads();
    for (int i = tid; i < 24 * 128; i += 256) {
        int rb = i >> 7, c = (i & 127) * 8;
        size_t wrow = (size_t)((rb >> 3) * 1024 + j0 + (rb & 7));
        *(uint4*)(sWh + rb * WLD + c) = *(const uint4*)(g_Whh_h + wrow * Hh + c);
        *(uint4*)(sWl + rb * WLD + c) = *(const uint4*)(g_Whh_l + wrow * Hh + c);
    }

    int u = tid & 7, bA = tid >> 3;
    float hp0 = h_init[j0 + u], hp1 = hp0;
    int len0 = length[bA], len1 = length[bA + 32];
    float br = bhh[j0+u], bz = bhh[Hh+j0+u], bn = bhh[2*Hh+j0+u];
    float cr = bih[j0+u], cz = bih[Hh+j0+u], cn = bih[2*Hh+j0+u];
    __syncthreads();

    for (int t = 0; t < Ss; t++) {
        const bf16* hinH = &g_ch_h[t & 1][0];
        const bf16* hinL = &g_ch_l[t & 1][0];
        bf16* houtH = &g_ch_h[(t + 1) & 1][0];
        bf16* houtL = &g_ch_l[(t + 1) & 1][0];

        wmma::fragment<wmma::accumulator,16,16,16,float> acc;
        wmma::fill_fragment(acc, 0.f);

        auto issueA = [&](int kc, int stg) {
            bf16* dh = sA + (size_t)stg * ASTG;
            bf16* dl = dh + 64 * ALD;
#pragma unroll
            for (int i = 0; i < 4; i++) {
                int id = tid + 256 * i;
                int half = id >> 9;
                int e = id & 511;
                int r = e >> 3, c = (e & 7) * 8;
                const bf16* src = (half ? hinL : hinH) + r * Hh + kc * 64 + c;
                cpasync16((half ? dl : dh) + r * ALD + c, src);
            }
            cpcommit();
        };

        issueA(0, 0); issueA(1, 1); issueA(2, 2);
        for (int kc = 0; kc < 16; kc++) {
            if      (kc <= 13) cpwait<2>();
            else if (kc == 14) cpwait<1>();
            else               cpwait<0>();
            __syncthreads();
            if (kc + 3 < 16) issueA(kc + 3, (kc + 3) & 3);
            bf16* dh = sA + (size_t)(kc & 3) * ASTG;
            bf16* dl = dh + 64 * ALD;
#pragma unroll
            for (int ks = 0; ks < 4; ks++) {
                wmma::fragment<wmma::matrix_a,16,16,16,bf16,wmma::row_major> ah, al;
                wmma::fragment<wmma::matrix_b,16,16,16,bf16,wmma::col_major> bhf, blf;
                wmma::load_matrix_sync(ah, dh + (wr*16)*ALD + ks*16, ALD);
                wmma::load_matrix_sync(al, dl + (wr*16)*ALD + ks*16, ALD);
                wmma::load_matrix_sync(bhf, sWh + (wc*16)*WLD + kc*64 + ks*16, WLD);
                wmma::load_matrix_sync(blf, sWl + (wc*16)*WLD + kc*64 + ks*16, WLD);
                wmma::mma_sync(acc, ah, bhf, acc);
                wmma::mma_sync(acc, ah, blf, acc);
                wmma::mma_sync(acc, al, bhf, acc);
            }
        }
        __syncthreads();
        wmma::store_matrix_sync(ghsm + (wr*16)*36 + wc*16, acc, 36, wmma::mem_row_major);
        __syncthreads();

#pragma unroll
        for (int e2 = 0; e2 < 2; e2++) {
            int b = bA + e2 * 32;
            float hprev = e2 ? hp1 : hp0;
            int   len   = e2 ? len1 : len0;
            float ghr = ghsm[b*36 + u]      + br;
            float ghz = ghsm[b*36 + 8 + u]  + bz;
            float ghn = ghsm[b*36 + 16 + u] + bn;
            const float* GIt = g_GI + ((size_t)t * Bb + b) * H3 + j0 + u;
            float gir = GIt[0]     + cr;
            float giz = GIt[Hh]    + cz;
            float gin = GIt[2*Hh]  + cn;
            float rg = 1.f / (1.f + expf(-(gir + ghr)));
            float zg = 1.f / (1.f + expf(-(giz + ghz)));
            float ng = tanhf(gin + rg * ghn);
            float keep = (t < len) ? 1.f : 0.f;
            float hn = (ng + zg * (hprev - ng)) * keep;
            if (e2) hp1 = hn; else hp0 = hn;

            int j = j0 + u;
            bf16 hhi = __float2bfloat16(hn);
            bf16 hlo = __float2bfloat16(hn - __bfloat162float(hhi));
            houtH[b*Hh + j] = hhi;
            houtL[b*Hh + j] = hlo;
            size_t hx = ((size_t)t * Bb + b) * Hh + j;
            g_hsh[hx] = hhi;
            g_hsl[hx] = hlo;
            hs[((size_t)t * Bb + b) * 2048 + j] = hn;
        }

        if (t < Ss - 1) {
            __syncthreads();
            if (tid == 0) {
                __threadfence();
                atomicAdd(&g_count, 1u);
                unsigned target = (unsigned)(t + 1) * SCAN_BLOCKS;
                while (*(volatile unsigned*)&g_count < target)
                    __nanosleep(32);
                __threadfence();
            }
            __syncthreads();
        }
    }
}

__global__ void init_h_kernel(const float* __restrict__ h_init) {
    int idx = blockIdx.x * blockDim.x + threadIdx.x;
    float v = h_init[idx & (Hh - 1)];
    bf16 hi = __float2bfloat16(v);
    g_ch_h[0][idx] = hi;
    g_ch_l[0][idx] = __float2bfloat16(v - __bfloat162float(hi));
    if (idx == 0) g_count = 0;
}

__global__ void softmax_kernel(float* __restrict__ attn,
                               const int* __restrict__ post_length,
                               bf16* __restrict__ ah, bf16* __restrict__ al)
{
    extern __shared__ float smf[];
    int s = blockIdx.x;
    float* base = attn + (size_t)s * Ll * Bb;
    for (int i = threadIdx.x; i < Ll * Bb; i += 256) {
        int l = i >> 6, b = i & 63;
        smf[b * 260 + l] = base[i];
    }
    __syncthreads();
    {
        int b = threadIdx.x >> 2, q = threadIdx.x & 3;
        int plen = post_length[b];
        float* row = smf + b * 260;
        float m = -INFINITY;
        for (int l = q; l < plen; l += 4) m = fmaxf(m, row[l]);
        m = fmaxf(m, __shfl_xor_sync(0xffffffff, m, 1));
        m = fmaxf(m, __shfl_xor_sync(0xffffffff, m, 2));
        float sum = 0.f;
        for (int l = q; l < plen; l += 4) {
            float e = expf(row[l] - m);
            row[l] = e;
            sum += e;
        }
        sum += __shfl_xor_sync(0xffffffff, sum, 1);
        sum += __shfl_xor_sync(0xffffffff, sum, 2);
        float inv = 1.f / sum;
        for (int l = q; l < plen; l += 4) row[l] *= inv;
        for (int l = plen + q; l < Ll; l += 4) row[l] = 0.f;
    }
    __syncthreads();
    for (int i = threadIdx.x; i < Ll * Bb; i += 256) {
        int l = i >> 6, b = i & 63;
        base[i] = smf[b * 260 + l];
    }
    for (int i = threadIdx.x; i < Ll * Bb; i += 256) {
        int b = i >> 8, l = i & 255;
        float v = smf[b * 260 + l];
        bf16 hi = __float2bfloat16(v);
        size_t off = (size_t)b * (Ss * Ll) + (size_t)s * Ll + l;
        ah[off] = hi;
        al[off] = __float2bfloat16(v - __bfloat162float(hi));
    }
}

__global__ void copy_hlast_kernel(const float* __restrict__ hs, float* __restrict__ out) {
    int idx = blockIdx.x * blockDim.x + threadIdx.x;
    int b = idx >> 10, j = idx & 1023;
    out[idx] = hs[((size_t)255 * Bb + b) * 2048 + j];
}

extern "C" void kernel_launch(void* const* d_in, const int* in_sizes, int n_in,
                              void* d_out, int out_size)
{
    (void)in_sizes; (void)n_in; (void)out_size;
    const float* incoming = (const float*)d_in[0];
    const float* post     = (const float*)d_in[1];
    const float* h_init   = (const float*)d_in[2];
    const float* W_ih     = (const float*)d_in[3];
    const float* W_hh     = (const float*)d_in[4];
    const float* b_ih     = (const float*)d_in[5];
    const float* b_hh     = (const float*)d_in[6];
    const float* Wq       = (const float*)d_in[7];
    const float* bq       = (const float*)d_in[8];
    const int*   length   = (const int*)d_in[9];
    const int*   plen     = (const int*)d_in[10];

    float* out    = (float*)d_out;
    float* h_last = out;
    float* hs     = out + (size_t)Bb * Hh;
    float* attn   = hs + (size_t)Ss * Bb * 2048;

    float *GI;
    bf16 *inch, *incl, *WihH, *WihL, *WhhH, *WhhL, *WqH, *WqL;
    bf16 *Qh, *Ql, *ph, *pl, *ah, *al, *hsH, *hsL;
    cudaGetSymbolAddress((void**)&GI,   g_GI);
    cudaGetSymbolAddress((void**)&inch, g_inch);
    cudaGetSymbolAddress((void**)&incl, g_incl);
    cudaGetSymbolAddress((void**)&WihH, g_Wih_h);
    cudaGetSymbolAddress((void**)&WihL, g_Wih_l);
    cudaGetSymbolAddress((void**)&WhhH, g_Whh_h);
    cudaGetSymbolAddress((void**)&WhhL, g_Whh_l);
    cudaGetSymbolAddress((void**)&WqH,  g_Wq_h);
    cudaGetSymbolAddress((void**)&WqL,  g_Wq_l);
    cudaGetSymbolAddress((void**)&Qh,   g_Qh);
    cudaGetSymbolAddress((void**)&Ql,   g_Ql);
    cudaGetSymbolAddress((void**)&ph,   g_ph);
    cudaGetSymbolAddress((void**)&pl,   g_pl);
    cudaGetSymbolAddress((void**)&ah,   g_ah);
    cudaGetSymbolAddress((void**)&al,   g_al);
    cudaGetSymbolAddress((void**)&hsH,  g_hsh);
    cudaGetSymbolAddress((void**)&hsL,  g_hsl);

    const int GEMM_SMEM = 4 * 4 * 128 * 40 * (int)sizeof(bf16);          // 163840
    const int NN_SMEM   = 2 * (2*128*40 + 2*32*136) * (int)sizeof(bf16); // 75776
    const int SCAN_SMEM = (2*32*1032 + 4*2*64*72) * (int)sizeof(bf16);   // 205824
    const int SFT_SMEM  = 64 * 260 * (int)sizeof(float);                 // 66560
    cudaFuncSetAttribute(wmma_split_nt,
                         cudaFuncAttributeMaxDynamicSharedMemorySize, GEMM_SMEM);
    cudaFuncSetAttribute(wmma_split_nn,
                         cudaFuncAttributeMaxDynamicSharedMemorySize, NN_SMEM);
    cudaFuncSetAttribute(gru_scan,
                         cudaFuncAttributeMaxDynamicSharedMemorySize, SCAN_SMEM);
    cudaFuncSetAttribute(softmax_kernel,
                         cudaFuncAttributeMaxDynamicSharedMemorySize, SFT_SMEM);

    init_h_kernel<<<256, 256>>>(h_init);
    split_kernel<<<(Ss*Bb*Ii + 255)/256, 256>>>(incoming, inch, incl, Ss*Bb*Ii);
    split_kernel<<<(H3*Ii + 255)/256, 256>>>(W_ih, WihH, WihL, H3*Ii);
    split_kernel<<<(H3*Hh + 255)/256, 256>>>(W_hh, WhhH, WhhL, H3*Hh);
    split_kernel<<<(Pp*Hh + 255)/256, 256>>>(Wq, WqH, WqL, Pp*Hh);

    // GI = incoming @ W_ih^T
    wmma_split_nt<<<dim3(Ss*Bb/128, H3/128, 1), 256, GEMM_SMEM>>>(
        inch, incl, Ii, 0,  WihH, WihL, Ii, 0,
        GI, H3, 1, 0,  nullptr, nullptr, nullptr,  Ii);

    split_kernel<<<(Ll*Bb*Pp + 255)/256, 256>>>(post, ph, pl, Ll*Bb*Pp);

    gru_scan<<<SCAN_BLOCKS, 256, SCAN_SMEM>>>(b_ih, b_hh, length, h_init, hs);

    // Q = h_hist @ Wq^T + bq -> split (fused epilogue)
    wmma_split_nt<<<dim3(Ss*Bb/128, Pp/128, 1), 256, GEMM_SMEM>>>(
        hsH, hsL, Hh, 0,  WqH, WqL, Hh, 0,
        nullptr, Pp, 1, 0,  bq, Qh, Ql,  Hh);

    // scores[s,l,b] = Q_b[s,:] . post_b[l,:]
    wmma_split_nt<<<dim3(Ss/128, Ll/128, Bb), 256, GEMM_SMEM>>>(
        Qh, Ql, (long)Bb*Pp, Pp,  ph, pl, (long)Bb*Pp, Pp,
        attn, (long)Ll*Bb, Bb, 1,  nullptr, nullptr, nullptr,  Pp);

    softmax_kernel<<<Ss, 256, SFT_SMEM>>>(attn, plen, ah, al);

    wmma_split_nn<<<dim3(Ss/128, Pp/128, Bb), 256, NN_SMEM>>>(
        ah, al, Ll, (long)Ss*Ll,
        ph, pl, (long)Bb*Pp, Pp,
        hs + Hh, (long)Bb*2048, 2048,  Ll);

    copy_hlast_kernel<<<256, 256>>>(hs, h_last);
}

// round 13
// speedup vs baseline: 1.1723x; 1.1723x over previous
#include <cuda_runtime.h>
#include <cuda_fp16.h>
#include <mma.h>
#include <math.h>

using namespace nvcuda;
typedef __half hf;

#define Ss 256
#define Bb 64
#define Ii 1024
#define Hh 1024
#define H3 3072
#define Pp 1024
#define Ll 256
#define SCAN_BLOCKS 128

__device__ float g_GI[(size_t)Ss * Bb * H3];
__device__ hf g_inch[(size_t)Ss * Bb * Ii], g_incl[(size_t)Ss * Bb * Ii];
__device__ hf g_Wih[(size_t)H3 * Ii];                       // single fp16 (2-pass GI)
__device__ hf g_Whh_h[(size_t)H3 * Hh], g_Whh_l[(size_t)H3 * Hh];
__device__ hf g_Wq_h [(size_t)Pp * Hh], g_Wq_l [(size_t)Pp * Hh];
__device__ hf g_Qh[(size_t)Ss * Bb * Pp], g_Ql[(size_t)Ss * Bb * Pp];
__device__ hf g_ph[(size_t)Ll * Bb * Pp], g_pl[(size_t)Ll * Bb * Pp];
__device__ hf g_ah[(size_t)Bb * Ss * Ll], g_al[(size_t)Bb * Ss * Ll];
__device__ hf g_ch_h[2][Bb * Hh], g_ch_l[2][Bb * Hh];
__device__ hf g_hsh[(size_t)Ss * Bb * Hh], g_hsl[(size_t)Ss * Bb * Hh];
__device__ unsigned g_count;

__device__ __forceinline__ void cpasync16(void* dst, const void* src) {
    unsigned d = (unsigned)__cvta_generic_to_shared(dst);
    asm volatile("cp.async.cg.shared.global [%0], [%1], 16;\n" :: "r"(d), "l"(src));
}
__device__ __forceinline__ void cpcommit() { asm volatile("cp.async.commit_group;\n"); }
template<int N> __device__ __forceinline__ void cpwait() {
    asm volatile("cp.async.wait_group %0;\n" :: "n"(N));
}

__global__ void split2_kernel(const float* __restrict__ x,
                              hf* __restrict__ hi, hf* __restrict__ lo, int n)
{
    int i = blockIdx.x * blockDim.x + threadIdx.x;
    if (i < n) {
        float v = x[i];
        hf h = __float2half_rn(v);
        hi[i] = h;
        lo[i] = __float2half_rn(v - __half2float(h));
    }
}
__global__ void tofp16_kernel(const float* __restrict__ x, hf* __restrict__ y, int n)
{
    int i = blockIdx.x * blockDim.x + threadIdx.x;
    if (i < n) y[i] = __float2half_rn(x[i]);
}

// ---- fp16 NT GEMM: C = (Ah+Al) * (Bh[+Bl])^T; 3-pass if Bl, else 2-pass ----
// 128x128 tile, BK=32, 4-stage race-free cp.async, 256 thr, warp tile 64x32.
__global__ void __launch_bounds__(256)
wmma_split_nt(const hf* __restrict__ Ah, const hf* __restrict__ Al,
              long ldaR, long batchA,
              const hf* __restrict__ Bh, const hf* __restrict__ Bl,
              long ldbR, long batchB,
              float* __restrict__ C, long ldcR, long cstr, long batchC,
              const float* __restrict__ bias,
              hf* __restrict__ Ch, hf* __restrict__ Cl,
              int K)
{
    extern __shared__ hf sm[];
    const int LD = 40;
    const int STG = 4 * 128 * LD;              // 20480 hf per stage
    int z = blockIdx.z;
    Ah += (size_t)z * batchA;  Al += (size_t)z * batchA;
    Bh += (size_t)z * batchB;  if (Bl) Bl += (size_t)z * batchB;
    if (C) C += (size_t)z * batchC;
    int m0 = blockIdx.x * 128, n0 = blockIdx.y * 128;
    int tid = threadIdx.x;
    int w = tid >> 5, wr = w >> 2, wc = w & 3;
    bool has3 = (Bl != nullptr);

    wmma::fragment<wmma::accumulator,16,16,16,float> acc[4][2];
#pragma unroll
    for (int i = 0; i < 4; i++)
#pragma unroll
        for (int j = 0; j < 2; j++) wmma::fill_fragment(acc[i][j], 0.f);

    auto issue = [&](int kt) {
        hf* base = sm + (size_t)(kt & 3) * STG;
        int k0 = kt * 32;
#pragma unroll
        for (int i = 0; i < 8; i++) {
            int id = tid + 256 * i;            // 0..2047
            int buf = id >> 9;                 // 0:Ah 1:Al 2:Bh 3:Bl
            if (buf == 3 && !has3) continue;
            int e = id & 511;
            int r = e >> 2, c = (e & 3) * 8;
            const hf* src;
            if      (buf == 0) src = Ah + (size_t)(m0 + r) * ldaR + k0 + c;
            else if (buf == 1) src = Al + (size_t)(m0 + r) * ldaR + k0 + c;
            else if (buf == 2) src = Bh + (size_t)(n0 + r) * ldbR + k0 + c;
            else               src = Bl + (size_t)(n0 + r) * ldbR + k0 + c;
            cpasync16(base + (size_t)buf * 128 * LD + r * LD + c, src);
        }
        cpcommit();
    };

    int KT = K / 32;
    issue(0); if (KT > 1) issue(1); if (KT > 2) issue(2);
    for (int kt = 0; kt < KT; kt++) {
        if      (kt < KT - 2)  cpwait<2>();
        else if (kt == KT - 2) cpwait<1>();
        else                   cpwait<0>();
        __syncthreads();
        if (kt + 3 < KT) issue(kt + 3);
        hf* base = sm + (size_t)(kt & 3) * STG;
        hf *sAh_ = base, *sAl_ = base + 128*LD, *sBh_ = base + 2*128*LD, *sBl_ = base + 3*128*LD;
#pragma unroll
        for (int ks = 0; ks < 2; ks++) {
            wmma::fragment<wmma::matrix_a,16,16,16,hf,wmma::row_major> ah[4], al[4];
            wmma::fragment<wmma::matrix_b,16,16,16,hf,wmma::col_major> bh[2], bl[2];
#pragma unroll
            for (int i = 0; i < 4; i++) {
                wmma::load_matrix_sync(ah[i], sAh_ + (wr*64 + i*16)*LD + ks*16, LD);
                wmma::load_matrix_sync(al[i], sAl_ + (wr*64 + i*16)*LD + ks*16, LD);
            }
#pragma unroll
            for (int j = 0; j < 2; j++) {
                wmma::load_matrix_sync(bh[j], sBh_ + (wc*32 + j*16)*LD + ks*16, LD);
                if (has3)
                    wmma::load_matrix_sync(bl[j], sBl_ + (wc*32 + j*16)*LD + ks*16, LD);
            }
#pragma unroll
            for (int i = 0; i < 4; i++)
#pragma unroll
                for (int j = 0; j < 2; j++) {
                    wmma::mma_sync(acc[i][j], ah[i], bh[j], acc[i][j]);
                    wmma::mma_sync(acc[i][j], al[i], bh[j], acc[i][j]);
                    if (has3)
                        wmma::mma_sync(acc[i][j], ah[i], bl[j], acc[i][j]);
                }
        }
    }
    __syncthreads();

    if (Ch) {
        float* smf = (float*)sm;
#pragma unroll
        for (int i = 0; i < 4; i++)
#pragma unroll
            for (int j = 0; j < 2; j++)
                wmma::store_matrix_sync(smf + (wr*64 + i*16)*128 + wc*32 + j*16,
                                        acc[i][j], 128, wmma::mem_row_major);
        __syncthreads();
        for (int e = tid; e < 16384; e += 256) {
            int m = e >> 7, n = e & 127;
            float v = smf[e] + (bias ? bias[n0 + n] : 0.f);
            hf hi = __float2half_rn(v);
            size_t off = (size_t)(m0 + m) * ldcR + n0 + n;
            Ch[off] = hi;
            Cl[off] = __float2half_rn(v - __half2float(hi));
        }
    } else if (cstr == 1) {
#pragma unroll
        for (int i = 0; i < 4; i++)
#pragma unroll
            for (int j = 0; j < 2; j++)
                wmma::store_matrix_sync(
                    C + (size_t)(m0 + wr*64 + i*16) * ldcR + n0 + wc*32 + j*16,
                    acc[i][j], ldcR, wmma::mem_row_major);
    } else {
        float* smf = (float*)sm;
#pragma unroll
        for (int i = 0; i < 4; i++)
#pragma unroll
            for (int j = 0; j < 2; j++)
                wmma::store_matrix_sync(smf + (wr*64 + i*16)*128 + wc*32 + j*16,
                                        acc[i][j], 128, wmma::mem_row_major);
        __syncthreads();
        for (int e = tid; e < 16384; e += 256) {
            int m = e >> 7, n = e & 127;
            C[(size_t)(m0 + m) * ldcR + (size_t)(n0 + n) * cstr] = smf[e];
        }
    }
}

// ---- fp16 3-pass NN GEMM: C = (Ah+Al)*(Bh+Bl), B row-major [K,N] ----
__global__ void __launch_bounds__(256)
wmma_split_nn(const hf* __restrict__ Ah, const hf* __restrict__ Al,
              long ldaR, long batchA,
              const hf* __restrict__ Bh, const hf* __restrict__ Bl,
              long ldbR, long batchB,
              float* __restrict__ C, long ldcR, long batchC, int K)
{
    extern __shared__ hf sm[];
    const int ALD = 40, BLD = 136;
    const int STG = 2*128*ALD + 2*32*BLD;
    int z = blockIdx.z;
    Ah += (size_t)z * batchA;  Al += (size_t)z * batchA;
    Bh += (size_t)z * batchB;  Bl += (size_t)z * batchB;
    C  += (size_t)z * batchC;
    int m0 = blockIdx.x * 128, n0 = blockIdx.y * 128;
    int tid = threadIdx.x;
    int w = tid >> 5, wr = w >> 2, wc = w & 3;

    wmma::fragment<wmma::accumulator,16,16,16,float> acc[4][2];
#pragma unroll
    for (int i = 0; i < 4; i++)
#pragma unroll
        for (int j = 0; j < 2; j++) wmma::fill_fragment(acc[i][j], 0.f);

    auto issue = [&](int kt, int stg) {
        hf* base = sm + (size_t)stg * STG;
        hf *dAh = base, *dAl = base + 128*ALD, *dBh = base + 2*128*ALD, *dBl = base + 2*128*ALD + 32*BLD;
        int k0 = kt * 32;
#pragma unroll
        for (int i = 0; i < 8; i++) {
            int id = tid + 256 * i;
            int buf = id >> 9;
            int e = id & 511;
            if (buf < 2) {
                int r = e >> 2, c = (e & 3) * 8;
                const hf* src = (buf ? Al : Ah) + (size_t)(m0 + r) * ldaR + k0 + c;
                cpasync16((buf ? dAl : dAh) + r * ALD + c, src);
            } else {
                int r = e >> 4, c = (e & 15) * 8;
                const hf* src = (buf == 3 ? Bl : Bh) + (size_t)(k0 + r) * ldbR + n0 + c;
                cpasync16((buf == 3 ? dBl : dBh) + r * BLD + c, src);
            }
        }
        cpcommit();
    };

    int KT = K / 32;
    issue(0, 0);
    for (int kt = 0; kt < KT; kt++) {
        if (kt + 1 < KT) { issue(kt + 1, (kt + 1) & 1); cpwait<1>(); }
        else             { cpwait<0>(); }
        __syncthreads();
        hf* base = sm + (size_t)(kt & 1) * STG;
        hf *sAh_ = base, *sAl_ = base + 128*ALD, *sBh_ = base + 2*128*ALD, *sBl_ = sBh_ + 32*BLD;
#pragma unroll
        for (int ks = 0; ks < 2; ks++) {
            wmma::fragment<wmma::matrix_a,16,16,16,hf,wmma::row_major> ah[4], al[4];
            wmma::fragment<wmma::matrix_b,16,16,16,hf,wmma::row_major> bh[2], bl[2];
#pragma unroll
            for (int i = 0; i < 4; i++) {
                wmma::load_matrix_sync(ah[i], sAh_ + (wr*64 + i*16)*ALD + ks*16, ALD);
                wmma::load_matrix_sync(al[i], sAl_ + (wr*64 + i*16)*ALD + ks*16, ALD);
            }
#pragma unroll
            for (int j = 0; j < 2; j++) {
                wmma::load_matrix_sync(bh[j], sBh_ + (ks*16)*BLD + wc*32 + j*16, BLD);
                wmma::load_matrix_sync(bl[j], sBl_ + (ks*16)*BLD + wc*32 + j*16, BLD);
            }
#pragma unroll
            for (int i = 0; i < 4; i++)
#pragma unroll
                for (int j = 0; j < 2; j++) {
                    wmma::mma_sync(acc[i][j], ah[i], bh[j], acc[i][j]);
                    wmma::mma_sync(acc[i][j], ah[i], bl[j], acc[i][j]);
                    wmma::mma_sync(acc[i][j], al[i], bh[j], acc[i][j]);
                }
        }
        __syncthreads();
    }
#pragma unroll
    for (int i = 0; i < 4; i++)
#pragma unroll
        for (int j = 0; j < 2; j++)
            wmma::store_matrix_sync(
                C + (size_t)(m0 + wr*64 + i*16) * ldcR + n0 + wc*32 + j*16,
                acc[i][j], ldcR, wmma::mem_row_major);
}

// ---- persistent GRU scan, fp16 3-pass, W_hh hi+lo resident ----
__global__ void __launch_bounds__(256)
gru_scan(const float* __restrict__ bih, const float* __restrict__ bhh,
         const int* __restrict__ length, const float* __restrict__ h_init,
         float* __restrict__ hs)
{
    extern __shared__ hf ssm[];
    const int WLD = 1032, ALD = 72;
    const int ASTG = 2 * 64 * ALD;
    hf* sWh = ssm;
    hf* sWl = sWh + 32 * WLD;
    hf* sA  = sWl + 32 * WLD;
    float* ghsm = (float*)sA;

    int tid = threadIdx.x;
    int w = tid >> 5, wr = w & 3, wc = w >> 2;
    int j0 = blockIdx.x * 8;

    for (int i = tid; i < 32 * WLD; i += 256) {
        sWh[i] = __float2half_rn(0.f);
        sWl[i] = __float2half_rn(0.f);
    }
    __syncthreads();
    for (int i = tid; i < 24 * 128; i += 256) {
        int rb = i >> 7, c = (i & 127) * 8;
        size_t wrow = (size_t)((rb >> 3) * 1024 + j0 + (rb & 7));
        *(uint4*)(sWh + rb * WLD + c) = *(const uint4*)(g_Whh_h + wrow * Hh + c);
        *(uint4*)(sWl + rb * WLD + c) = *(const uint4*)(g_Whh_l + wrow * Hh + c);
    }

    int u = tid & 7, bA = tid >> 3;
    float hp0 = h_init[j0 + u], hp1 = hp0;
    int len0 = length[bA], len1 = length[bA + 32];
    float br = bhh[j0+u], bz = bhh[Hh+j0+u], bn = bhh[2*Hh+j0+u];
    float cr = bih[j0+u], cz = bih[Hh+j0+u], cn = bih[2*Hh+j0+u];
    __syncthreads();

    for (int t = 0; t < Ss; t++) {
        const hf* hinH = &g_ch_h[t & 1][0];
        const hf* hinL = &g_ch_l[t & 1][0];
        hf* houtH = &g_ch_h[(t + 1) & 1][0];
        hf* houtL = &g_ch_l[(t + 1) & 1][0];

        wmma::fragment<wmma::accumulator,16,16,16,float> acc;
        wmma::fill_fragment(acc, 0.f);

        auto issueA = [&](int kc, int stg) {
            hf* dh = sA + (size_t)stg * ASTG;
            hf* dl = dh + 64 * ALD;
#pragma unroll
            for (int i = 0; i < 4; i++) {
                int id = tid + 256 * i;
                int half_ = id >> 9;
                int e = id & 511;
                int r = e >> 3, c = (e & 7) * 8;
                const hf* src = (half_ ? hinL : hinH) + r * Hh + kc * 64 + c;
                cpasync16((half_ ? dl : dh) + r * ALD + c, src);
            }
            cpcommit();
        };

        issueA(0, 0); issueA(1, 1); issueA(2, 2);
        for (int kc = 0; kc < 16; kc++) {
            if      (kc <= 13) cpwait<2>();
            else if (kc == 14) cpwait<1>();
            else               cpwait<0>();
            __syncthreads();
            if (kc + 3 < 16) issueA(kc + 3, (kc + 3) & 3);
            hf* dh = sA + (size_t)(kc & 3) * ASTG;
            hf* dl = dh + 64 * ALD;
#pragma unroll
            for (int ks = 0; ks < 4; ks++) {
                wmma::fragment<wmma::matrix_a,16,16,16,hf,wmma::row_major> ah, al;
                wmma::fragment<wmma::matrix_b,16,16,16,hf,wmma::col_major> bhf, blf;
                wmma::load_matrix_sync(ah, dh + (wr*16)*ALD + ks*16, ALD);
                wmma::load_matrix_sync(al, dl + (wr*16)*ALD + ks*16, ALD);
                wmma::load_matrix_sync(bhf, sWh + (wc*16)*WLD + kc*64 + ks*16, WLD);
                wmma::load_matrix_sync(blf, sWl + (wc*16)*WLD + kc*64 + ks*16, WLD);
                wmma::mma_sync(acc, ah, bhf, acc);
                wmma::mma_sync(acc, ah, blf, acc);
                wmma::mma_sync(acc, al, bhf, acc);
            }
        }
        __syncthreads();
        wmma::store_matrix_sync(ghsm + (wr*16)*36 + wc*16, acc, 36, wmma::mem_row_major);
        __syncthreads();

#pragma unroll
        for (int e2 = 0; e2 < 2; e2++) {
            int b = bA + e2 * 32;
            float hprev = e2 ? hp1 : hp0;
            int   len   = e2 ? len1 : len0;
            float ghr = ghsm[b*36 + u]      + br;
            float ghz = ghsm[b*36 + 8 + u]  + bz;
            float ghn = ghsm[b*36 + 16 + u] + bn;
            const float* GIt = g_GI + ((size_t)t * Bb + b) * H3 + j0 + u;
            float gir = GIt[0]     + cr;
            float giz = GIt[Hh]    + cz;
            float gin = GIt[2*Hh]  + cn;
            float rg = 1.f / (1.f + expf(-(gir + ghr)));
            float zg = 1.f / (1.f + expf(-(giz + ghz)));
            float ng = tanhf(gin + rg * ghn);
            float keep = (t < len) ? 1.f : 0.f;
            float hn = (ng + zg * (hprev - ng)) * keep;
            if (e2) hp1 = hn; else hp0 = hn;

            int j = j0 + u;
            hf hhi = __float2half_rn(hn);
            hf hlo = __float2half_rn(hn - __half2float(hhi));
            houtH[b*Hh + j] = hhi;
            houtL[b*Hh + j] = hlo;
            size_t hx = ((size_t)t * Bb + b) * Hh + j;
            g_hsh[hx] = hhi;
            g_hsl[hx] = hlo;
            hs[((size_t)t * Bb + b) * 2048 + j] = hn;
        }

        if (t < Ss - 1) {
            __syncthreads();
            if (tid == 0) {
                __threadfence();
                atomicAdd(&g_count, 1u);
                unsigned target = (unsigned)(t + 1) * SCAN_BLOCKS;
                while (atomicAdd(&g_count, 0u) < target)
                    __nanosleep(32);
                __threadfence();
            }
            __syncthreads();
        }
    }
}

__global__ void init_h_kernel(const float* __restrict__ h_init) {
    int idx = blockIdx.x * blockDim.x + threadIdx.x;
    float v = h_init[idx & (Hh - 1)];
    hf hi = __float2half_rn(v);
    g_ch_h[0][idx] = hi;
    g_ch_l[0][idx] = __float2half_rn(v - __half2float(hi));
    if (idx == 0) g_count = 0;
}

__global__ void softmax_kernel(float* __restrict__ attn,
                               const int* __restrict__ post_length,
                               hf* __restrict__ ah, hf* __restrict__ al)
{
    extern __shared__ float smf[];
    int s = blockIdx.x;
    float* base = attn + (size_t)s * Ll * Bb;
    for (int i = threadIdx.x; i < Ll * Bb; i += 256) {
        int l = i >> 6, b = i & 63;
        smf[b * 260 + l] = base[i];
    }
    __syncthreads();
    {
        int b = threadIdx.x >> 2, q = threadIdx.x & 3;
        int plen = post_length[b];
        float* row = smf + b * 260;
        float m = -INFINITY;
        for (int l = q; l < plen; l += 4) m = fmaxf(m, row[l]);
        m = fmaxf(m, __shfl_xor_sync(0xffffffff, m, 1));
        m = fmaxf(m, __shfl_xor_sync(0xffffffff, m, 2));
        float sum = 0.f;
        for (int l = q; l < plen; l += 4) {
            float e = expf(row[l] - m);
            row[l] = e;
            sum += e;
        }
        sum += __shfl_xor_sync(0xffffffff, sum, 1);
        sum += __shfl_xor_sync(0xffffffff, sum, 2);
        float inv = 1.f / sum;
        for (int l = q; l < plen; l += 4) row[l] *= inv;
        for (int l = plen + q; l < Ll; l += 4) row[l] = 0.f;
    }
    __syncthreads();
    for (int i = threadIdx.x; i < Ll * Bb; i += 256) {
        int l = i >> 6, b = i & 63;
        base[i] = smf[b * 260 + l];
    }
    for (int i = threadIdx.x; i < Ll * Bb; i += 256) {
        int b = i >> 8, l = i & 255;
        float v = smf[b * 260 + l];
        hf hi = __float2half_rn(v);
        size_t off = (size_t)b * (Ss * Ll) + (size_t)s * Ll + l;
        ah[off] = hi;
        al[off] = __float2half_rn(v - __half2float(hi));
    }
}

__global__ void copy_hlast_kernel(const float* __restrict__ hs, float* __restrict__ out) {
    int idx = blockIdx.x * blockDim.x + threadIdx.x;
    int b = idx >> 10, j = idx & 1023;
    out[idx] = hs[((size_t)255 * Bb + b) * 2048 + j];
}

extern "C" void kernel_launch(void* const* d_in, const int* in_sizes, int n_in,
                              void* d_out, int out_size)
{
    (void)in_sizes; (void)n_in; (void)out_size;
    const float* incoming = (const float*)d_in[0];
    const float* post     = (const float*)d_in[1];
    const float* h_init   = (const float*)d_in[2];
    const float* W_ih     = (const float*)d_in[3];
    const float* W_hh     = (const float*)d_in[4];
    const float* b_ih     = (const float*)d_in[5];
    const float* b_hh     = (const float*)d_in[6];
    const float* Wq       = (const float*)d_in[7];
    const float* bq       = (const float*)d_in[8];
    const int*   length   = (const int*)d_in[9];
    const int*   plen     = (const int*)d_in[10];

    float* out    = (float*)d_out;
    float* h_last = out;
    float* hs     = out + (size_t)Bb * Hh;
    float* attn   = hs + (size_t)Ss * Bb * 2048;

    float *GI;
    hf *inch, *incl, *Wih, *WhhH, *WhhL, *WqH, *WqL;
    hf *Qh, *Ql, *ph, *pl, *ah, *al, *hsH, *hsL;
    cudaGetSymbolAddress((void**)&GI,   g_GI);
    cudaGetSymbolAddress((void**)&inch, g_inch);
    cudaGetSymbolAddress((void**)&incl, g_incl);
    cudaGetSymbolAddress((void**)&Wih,  g_Wih);
    cudaGetSymbolAddress((void**)&WhhH, g_Whh_h);
    cudaGetSymbolAddress((void**)&WhhL, g_Whh_l);
    cudaGetSymbolAddress((void**)&WqH,  g_Wq_h);
    cudaGetSymbolAddress((void**)&WqL,  g_Wq_l);
    cudaGetSymbolAddress((void**)&Qh,   g_Qh);
    cudaGetSymbolAddress((void**)&Ql,   g_Ql);
    cudaGetSymbolAddress((void**)&ph,   g_ph);
    cudaGetSymbolAddress((void**)&pl,   g_pl);
    cudaGetSymbolAddress((void**)&ah,   g_ah);
    cudaGetSymbolAddress((void**)&al,   g_al);
    cudaGetSymbolAddress((void**)&hsH,  g_hsh);
    cudaGetSymbolAddress((void**)&hsL,  g_hsl);

    const int NT_SMEM   = 4 * 4 * 128 * 40 * (int)sizeof(hf);           // 163840
    const int NN_SMEM   = 2 * (2*128*40 + 2*32*136) * (int)sizeof(hf);  // 75776
    const int SCAN_SMEM = (2*32*1032 + 4*2*64*72) * (int)sizeof(hf);    // 205824
    const int SFT_SMEM  = 64 * 260 * (int)sizeof(float);                // 66560
    cudaFuncSetAttribute(wmma_split_nt,
                         cudaFuncAttributeMaxDynamicSharedMemorySize, NT_SMEM);
    cudaFuncSetAttribute(wmma_split_nn,
                         cudaFuncAttributeMaxDynamicSharedMemorySize, NN_SMEM);
    cudaFuncSetAttribute(gru_scan,
                         cudaFuncAttributeMaxDynamicSharedMemorySize, SCAN_SMEM);
    cudaFuncSetAttribute(softmax_kernel,
                         cudaFuncAttributeMaxDynamicSharedMemorySize, SFT_SMEM);

    init_h_kernel<<<256, 256>>>(h_init);
    split2_kernel<<<(Ss*Bb*Ii + 255)/256, 256>>>(incoming, inch, incl, Ss*Bb*Ii);
    tofp16_kernel<<<(H3*Ii + 255)/256, 256>>>(W_ih, Wih, H3*Ii);
    split2_kernel<<<(H3*Hh + 255)/256, 256>>>(W_hh, WhhH, WhhL, H3*Hh);
    split2_kernel<<<(Pp*Hh + 255)/256, 256>>>(Wq, WqH, WqL, Pp*Hh);

    // GI = incoming @ W_ih^T  (2-pass: the one reduced-precision source)
    wmma_split_nt<<<dim3(Ss*Bb/128, H3/128, 1), 256, NT_SMEM>>>(
        inch, incl, Ii, 0,  Wih, nullptr, Ii, 0,
        GI, H3, 1, 0,  nullptr, nullptr, nullptr,  Ii);

    split2_kernel<<<(Ll*Bb*Pp + 255)/256, 256>>>(post, ph, pl, Ll*Bb*Pp);

    gru_scan<<<SCAN_BLOCKS, 256, SCAN_SMEM>>>(b_ih, b_hh, length, h_init, hs);

    // Q = h_hist @ Wq^T + bq -> split (3-pass, fused epilogue)
    wmma_split_nt<<<dim3(Ss*Bb/128, Pp/128, 1), 256, NT_SMEM>>>(
        hsH, hsL, Hh, 0,  WqH, WqL, Hh, 0,
        nullptr, Pp, 1, 0,  bq, Qh, Ql,  Hh);

    // scores[s,l,b] = Q_b[s,:] . post_b[l,:]  (3-pass)
    wmma_split_nt<<<dim3(Ss/128, Ll/128, Bb), 256, NT_SMEM>>>(
        Qh, Ql, (long)Bb*Pp, Pp,  ph, pl, (long)Bb*Pp, Pp,
        attn, (long)Ll*Bb, Bb, 1,  nullptr, nullptr, nullptr,  Pp);

    softmax_kernel<<<Ss, 256, SFT_SMEM>>>(attn, plen, ah, al);

    // context = attn @ post (3-pass) -> hs[:, :, H:2H]
    wmma_split_nn<<<dim3(Ss/128, Pp/128, Bb), 256, NN_SMEM>>>(
        ah, al, Ll, (long)Ss*Ll,
        ph, pl, (long)Bb*Pp, Pp,
        hs + Hh, (long)Bb*2048, 2048,  Ll);

    copy_hlast_kernel<<<256, 256>>>(hs, h_last);
}

// round 14
// speedup vs baseline: 1.2102x; 1.0323x over previous
#include <cuda_runtime.h>
#include <cuda_fp16.h>
#include <mma.h>
#include <math.h>

using namespace nvcuda;
typedef __half hf;

#define Ss 256
#define Bb 64
#define Ii 1024
#define Hh 1024
#define H3 3072
#define Pp 1024
#define Ll 256
#define SCAN_BLOCKS 128

__device__ float g_GI[(size_t)Ss * Bb * H3];
__device__ hf g_inch[(size_t)Ss * Bb * Ii], g_incl[(size_t)Ss * Bb * Ii];
__device__ hf g_Wih[(size_t)H3 * Ii];                       // single fp16 (2-pass GI)
__device__ hf g_Whh_h[(size_t)H3 * Hh], g_Whh_l[(size_t)H3 * Hh];
__device__ hf g_Wq_h [(size_t)Pp * Hh], g_Wq_l [(size_t)Pp * Hh];
__device__ hf g_Qh[(size_t)Ss * Bb * Pp], g_Ql[(size_t)Ss * Bb * Pp];
__device__ hf g_ph[(size_t)Ll * Bb * Pp], g_pl[(size_t)Ll * Bb * Pp];
__device__ hf g_ah[(size_t)Bb * Ss * Ll], g_al[(size_t)Bb * Ss * Ll];
__device__ hf g_ch_h[2][Bb * Hh], g_ch_l[2][Bb * Hh];
__device__ hf g_hsh[(size_t)Ss * Bb * Hh], g_hsl[(size_t)Ss * Bb * Hh];
__device__ unsigned g_count;

__device__ __forceinline__ void cpasync16(void* dst, const void* src) {
    unsigned d = (unsigned)__cvta_generic_to_shared(dst);
    asm volatile("cp.async.cg.shared.global [%0], [%1], 16;\n" :: "r"(d), "l"(src));
}
__device__ __forceinline__ void cpcommit() { asm volatile("cp.async.commit_group;\n"); }
template<int N> __device__ __forceinline__ void cpwait() {
    asm volatile("cp.async.wait_group %0;\n" :: "n"(N));
}

__global__ void split2_kernel(const float* __restrict__ x,
                              hf* __restrict__ hi, hf* __restrict__ lo, int n)
{
    int i = blockIdx.x * blockDim.x + threadIdx.x;
    if (i < n) {
        float v = x[i];
        hf h = __float2half_rn(v);
        hi[i] = h;
        lo[i] = __float2half_rn(v - __half2float(h));
    }
}
__global__ void tofp16_kernel(const float* __restrict__ x, hf* __restrict__ y, int n)
{
    int i = blockIdx.x * blockDim.x + threadIdx.x;
    if (i < n) y[i] = __float2half_rn(x[i]);
}

// ---- fp16 NT GEMM: C = (Ah+Al) * (Bh[+Bl])^T; 3-pass if Bl, else 2-pass ----
// 128x128 tile, BK=32, 4-stage race-free cp.async, 256 thr, warp tile 64x32.
__global__ void __launch_bounds__(256)
wmma_split_nt(const hf* __restrict__ Ah, const hf* __restrict__ Al,
              long ldaR, long batchA,
              const hf* __restrict__ Bh, const hf* __restrict__ Bl,
              long ldbR, long batchB,
              float* __restrict__ C, long ldcR, long cstr, long batchC,
              const float* __restrict__ bias,
              hf* __restrict__ Ch, hf* __restrict__ Cl,
              int K)
{
    extern __shared__ hf sm[];
    const int LD = 40;
    const int STG = 4 * 128 * LD;              // 20480 hf per stage
    int z = blockIdx.z;
    Ah += (size_t)z * batchA;  Al += (size_t)z * batchA;
    Bh += (size_t)z * batchB;  if (Bl) Bl += (size_t)z * batchB;
    if (C) C += (size_t)z * batchC;
    int m0 = blockIdx.x * 128, n0 = blockIdx.y * 128;
    int tid = threadIdx.x;
    int w = tid >> 5, wr = w >> 2, wc = w & 3;
    bool has3 = (Bl != nullptr);

    wmma::fragment<wmma::accumulator,16,16,16,float> acc[4][2];
#pragma unroll
    for (int i = 0; i < 4; i++)
#pragma unroll
        for (int j = 0; j < 2; j++) wmma::fill_fragment(acc[i][j], 0.f);

    auto issue = [&](int kt) {
        hf* base = sm + (size_t)(kt & 3) * STG;
        int k0 = kt * 32;
#pragma unroll
        for (int i = 0; i < 8; i++) {
            int id = tid + 256 * i;            // 0..2047
            int buf = id >> 9;                 // 0:Ah 1:Al 2:Bh 3:Bl
            if (buf == 3 && !has3) continue;
            int e = id & 511;
            int r = e >> 2, c = (e & 3) * 8;
            const hf* src;
            if      (buf == 0) src = Ah + (size_t)(m0 + r) * ldaR + k0 + c;
            else if (buf == 1) src = Al + (size_t)(m0 + r) * ldaR + k0 + c;
            else if (buf == 2) src = Bh + (size_t)(n0 + r) * ldbR + k0 + c;
            else               src = Bl + (size_t)(n0 + r) * ldbR + k0 + c;
            cpasync16(base + (size_t)buf * 128 * LD + r * LD + c, src);
        }
        cpcommit();
    };

    int KT = K / 32;
    issue(0); if (KT > 1) issue(1); if (KT > 2) issue(2);
    for (int kt = 0; kt < KT; kt++) {
        if      (kt < KT - 2)  cpwait<2>();
        else if (kt == KT - 2) cpwait<1>();
        else                   cpwait<0>();
        __syncthreads();
        if (kt + 3 < KT) issue(kt + 3);
        hf* base = sm + (size_t)(kt & 3) * STG;
        hf *sAh_ = base, *sAl_ = base + 128*LD, *sBh_ = base + 2*128*LD, *sBl_ = base + 3*128*LD;
#pragma unroll
        for (int ks = 0; ks < 2; ks++) {
            wmma::fragment<wmma::matrix_a,16,16,16,hf,wmma::row_major> ah[4], al[4];
            wmma::fragment<wmma::matrix_b,16,16,16,hf,wmma::col_major> bh[2], bl[2];
#pragma unroll
            for (int i = 0; i < 4; i++) {
                wmma::load_matrix_sync(ah[i], sAh_ + (wr*64 + i*16)*LD + ks*16, LD);
                wmma::load_matrix_sync(al[i], sAl_ + (wr*64 + i*16)*LD + ks*16, LD);
            }
#pragma unroll
            for (int j = 0; j < 2; j++) {
                wmma::load_matrix_sync(bh[j], sBh_ + (wc*32 + j*16)*LD + ks*16, LD);
                if (has3)
                    wmma::load_matrix_sync(bl[j], sBl_ + (wc*32 + j*16)*LD + ks*16, LD);
            }
#pragma unroll
            for (int i = 0; i < 4; i++)
#pragma unroll
                for (int j = 0; j < 2; j++) {
                    wmma::mma_sync(acc[i][j], ah[i], bh[j], acc[i][j]);
                    wmma::mma_sync(acc[i][j], al[i], bh[j], acc[i][j]);
                    if (has3)
                        wmma::mma_sync(acc[i][j], ah[i], bl[j], acc[i][j]);
                }
        }
    }
    __syncthreads();

    if (Ch) {
        float* smf = (float*)sm;
#pragma unroll
        for (int i = 0; i < 4; i++)
#pragma unroll
            for (int j = 0; j < 2; j++)
                wmma::store_matrix_sync(smf + (wr*64 + i*16)*128 + wc*32 + j*16,
                                        acc[i][j], 128, wmma::mem_row_major);
        __syncthreads();
        for (int e = tid; e < 16384; e += 256) {
            int m = e >> 7, n = e & 127;
            float v = smf[e] + (bias ? bias[n0 + n] : 0.f);
            hf hi = __float2half_rn(v);
            size_t off = (size_t)(m0 + m) * ldcR + n0 + n;
            Ch[off] = hi;
            Cl[off] = __float2half_rn(v - __half2float(hi));
        }
    } else if (cstr == 1) {
#pragma unroll
        for (int i = 0; i < 4; i++)
#pragma unroll
            for (int j = 0; j < 2; j++)
                wmma::store_matrix_sync(
                    C + (size_t)(m0 + wr*64 + i*16) * ldcR + n0 + wc*32 + j*16,
                    acc[i][j], ldcR, wmma::mem_row_major);
    } else {
        float* smf = (float*)sm;
#pragma unroll
        for (int i = 0; i < 4; i++)
#pragma unroll
            for (int j = 0; j < 2; j++)
                wmma::store_matrix_sync(smf + (wr*64 + i*16)*128 + wc*32 + j*16,
                                        acc[i][j], 128, wmma::mem_row_major);
        __syncthreads();
        for (int e = tid; e < 16384; e += 256) {
            int m = e >> 7, n = e & 127;
            C[(size_t)(m0 + m) * ldcR + (size_t)(n0 + n) * cstr] = smf[e];
        }
    }
}

// ---- fp16 3-pass NN GEMM: C = (Ah+Al)*(Bh+Bl), B row-major [K,N] ----
__global__ void __launch_bounds__(256)
wmma_split_nn(const hf* __restrict__ Ah, const hf* __restrict__ Al,
              long ldaR, long batchA,
              const hf* __restrict__ Bh, const hf* __restrict__ Bl,
              long ldbR, long batchB,
              float* __restrict__ C, long ldcR, long batchC, int K)
{
    extern __shared__ hf sm[];
    const int ALD = 40, BLD = 136;
    const int STG = 2*128*ALD + 2*32*BLD;
    int z = blockIdx.z;
    Ah += (size_t)z * batchA;  Al += (size_t)z * batchA;
    Bh += (size_t)z * batchB;  Bl += (size_t)z * batchB;
    C  += (size_t)z * batchC;
    int m0 = blockIdx.x * 128, n0 = blockIdx.y * 128;
    int tid = threadIdx.x;
    int w = tid >> 5, wr = w >> 2, wc = w & 3;

    wmma::fragment<wmma::accumulator,16,16,16,float> acc[4][2];
#pragma unroll
    for (int i = 0; i < 4; i++)
#pragma unroll
        for (int j = 0; j < 2; j++) wmma::fill_fragment(acc[i][j], 0.f);

    auto issue = [&](int kt, int stg) {
        hf* base = sm + (size_t)stg * STG;
        hf *dAh = base, *dAl = base + 128*ALD, *dBh = base + 2*128*ALD, *dBl = base + 2*128*ALD + 32*BLD;
        int k0 = kt * 32;
#pragma unroll
        for (int i = 0; i < 8; i++) {
            int id = tid + 256 * i;
            int buf = id >> 9;
            int e = id & 511;
            if (buf < 2) {
                int r = e >> 2, c = (e & 3) * 8;
                const hf* src = (buf ? Al : Ah) + (size_t)(m0 + r) * ldaR + k0 + c;
                cpasync16((buf ? dAl : dAh) + r * ALD + c, src);
            } else {
                int r = e >> 4, c = (e & 15) * 8;
                const hf* src = (buf == 3 ? Bl : Bh) + (size_t)(k0 + r) * ldbR + n0 + c;
                cpasync16((buf == 3 ? dBl : dBh) + r * BLD + c, src);
            }
        }
        cpcommit();
    };

    int KT = K / 32;
    issue(0, 0);
    for (int kt = 0; kt < KT; kt++) {
        if (kt + 1 < KT) { issue(kt + 1, (kt + 1) & 1); cpwait<1>(); }
        else             { cpwait<0>(); }
        __syncthreads();
        hf* base = sm + (size_t)(kt & 1) * STG;
        hf *sAh_ = base, *sAl_ = base + 128*ALD, *sBh_ = base + 2*128*ALD, *sBl_ = sBh_ + 32*BLD;
#pragma unroll
        for (int ks = 0; ks < 2; ks++) {
            wmma::fragment<wmma::matrix_a,16,16,16,hf,wmma::row_major> ah[4], al[4];
            wmma::fragment<wmma::matrix_b,16,16,16,hf,wmma::row_major> bh[2], bl[2];
#pragma unroll
            for (int i = 0; i < 4; i++) {
                wmma::load_matrix_sync(ah[i], sAh_ + (wr*64 + i*16)*ALD + ks*16, ALD);
                wmma::load_matrix_sync(al[i], sAl_ + (wr*64 + i*16)*ALD + ks*16, ALD);
            }
#pragma unroll
            for (int j = 0; j < 2; j++) {
                wmma::load_matrix_sync(bh[j], sBh_ + (ks*16)*BLD + wc*32 + j*16, BLD);
                wmma::load_matrix_sync(bl[j], sBl_ + (ks*16)*BLD + wc*32 + j*16, BLD);
            }
#pragma unroll
            for (int i = 0; i < 4; i++)
#pragma unroll
                for (int j = 0; j < 2; j++) {
                    wmma::mma_sync(acc[i][j], ah[i], bh[j], acc[i][j]);
                    wmma::mma_sync(acc[i][j], ah[i], bl[j], acc[i][j]);
                    wmma::mma_sync(acc[i][j], al[i], bh[j], acc[i][j]);
                }
        }
        __syncthreads();
    }
#pragma unroll
    for (int i = 0; i < 4; i++)
#pragma unroll
        for (int j = 0; j < 2; j++)
            wmma::store_matrix_sync(
                C + (size_t)(m0 + wr*64 + i*16) * ldcR + n0 + wc*32 + j*16,
                acc[i][j], ldcR, wmma::mem_row_major);
}

// ---- persistent GRU scan, fp16 3-pass, W_hh hi+lo resident ----
// R14: 3 independent accumulators (one per pass) to break the HMMA RAW chain.
__global__ void __launch_bounds__(256)
gru_scan(const float* __restrict__ bih, const float* __restrict__ bhh,
         const int* __restrict__ length, const float* __restrict__ h_init,
         float* __restrict__ hs)
{
    extern __shared__ hf ssm[];
    const int WLD = 1032, ALD = 72;
    const int ASTG = 2 * 64 * ALD;
    hf* sWh = ssm;
    hf* sWl = sWh + 32 * WLD;
    hf* sA  = sWl + 32 * WLD;
    float* ghsm = (float*)sA;

    int tid = threadIdx.x;
    int w = tid >> 5, wr = w & 3, wc = w >> 2;
    int j0 = blockIdx.x * 8;

    for (int i = tid; i < 32 * WLD; i += 256) {
        sWh[i] = __float2half_rn(0.f);
        sWl[i] = __float2half_rn(0.f);
    }
    __syncthreads();
    for (int i = tid; i < 24 * 128; i += 256) {
        int rb = i >> 7, c = (i & 127) * 8;
        size_t wrow = (size_t)((rb >> 3) * 1024 + j0 + (rb & 7));
        *(uint4*)(sWh + rb * WLD + c) = *(const uint4*)(g_Whh_h + wrow * Hh + c);
        *(uint4*)(sWl + rb * WLD + c) = *(const uint4*)(g_Whh_l + wrow * Hh + c);
    }

    int u = tid & 7, bA = tid >> 3;
    float hp0 = h_init[j0 + u], hp1 = hp0;
    int len0 = length[bA], len1 = length[bA + 32];
    float br = bhh[j0+u], bz = bhh[Hh+j0+u], bn = bhh[2*Hh+j0+u];
    float cr = bih[j0+u], cz = bih[Hh+j0+u], cn = bih[2*Hh+j0+u];
    __syncthreads();

    for (int t = 0; t < Ss; t++) {
        const hf* hinH = &g_ch_h[t & 1][0];
        const hf* hinL = &g_ch_l[t & 1][0];
        hf* houtH = &g_ch_h[(t + 1) & 1][0];
        hf* houtL = &g_ch_l[(t + 1) & 1][0];

        wmma::fragment<wmma::accumulator,16,16,16,float> acc0, acc1, acc2;
        wmma::fill_fragment(acc0, 0.f);
        wmma::fill_fragment(acc1, 0.f);
        wmma::fill_fragment(acc2, 0.f);

        auto issueA = [&](int kc, int stg) {
            hf* dh = sA + (size_t)stg * ASTG;
            hf* dl = dh + 64 * ALD;
#pragma unroll
            for (int i = 0; i < 4; i++) {
                int id = tid + 256 * i;
                int half_ = id >> 9;
                int e = id & 511;
                int r = e >> 3, c = (e & 7) * 8;
                const hf* src = (half_ ? hinL : hinH) + r * Hh + kc * 64 + c;
                cpasync16((half_ ? dl : dh) + r * ALD + c, src);
            }
            cpcommit();
        };

        issueA(0, 0); issueA(1, 1); issueA(2, 2);
        for (int kc = 0; kc < 16; kc++) {
            if      (kc <= 13) cpwait<2>();
            else if (kc == 14) cpwait<1>();
            else               cpwait<0>();
            __syncthreads();
            if (kc + 3 < 16) issueA(kc + 3, (kc + 3) & 3);
            hf* dh = sA + (size_t)(kc & 3) * ASTG;
            hf* dl = dh + 64 * ALD;
#pragma unroll
            for (int ks = 0; ks < 4; ks++) {
                wmma::fragment<wmma::matrix_a,16,16,16,hf,wmma::row_major> ah, al;
                wmma::fragment<wmma::matrix_b,16,16,16,hf,wmma::col_major> bhf, blf;
                wmma::load_matrix_sync(ah, dh + (wr*16)*ALD + ks*16, ALD);
                wmma::load_matrix_sync(al, dl + (wr*16)*ALD + ks*16, ALD);
                wmma::load_matrix_sync(bhf, sWh + (wc*16)*WLD + kc*64 + ks*16, WLD);
                wmma::load_matrix_sync(blf, sWl + (wc*16)*WLD + kc*64 + ks*16, WLD);
                wmma::mma_sync(acc0, ah, bhf, acc0);   // 3 independent chains
                wmma::mma_sync(acc1, ah, blf, acc1);
                wmma::mma_sync(acc2, al, bhf, acc2);
            }
        }
#pragma unroll
        for (int i = 0; i < acc0.num_elements; i++)
            acc0.x[i] += acc1.x[i] + acc2.x[i];
        __syncthreads();
        wmma::store_matrix_sync(ghsm + (wr*16)*36 + wc*16, acc0, 36, wmma::mem_row_major);
        __syncthreads();

#pragma unroll
        for (int e2 = 0; e2 < 2; e2++) {
            int b = bA + e2 * 32;
            float hprev = e2 ? hp1 : hp0;
            int   len   = e2 ? len1 : len0;
            float ghr = ghsm[b*36 + u]      + br;
            float ghz = ghsm[b*36 + 8 + u]  + bz;
            float ghn = ghsm[b*36 + 16 + u] + bn;
            const float* GIt = g_GI + ((size_t)t * Bb + b) * H3 + j0 + u;
            float gir = GIt[0]     + cr;
            float giz = GIt[Hh]    + cz;
            float gin = GIt[2*Hh]  + cn;
            float rg = 1.f / (1.f + expf(-(gir + ghr)));
            float zg = 1.f / (1.f + expf(-(giz + ghz)));
            float ng = tanhf(gin + rg * ghn);
            float keep = (t < len) ? 1.f : 0.f;
            float hn = (ng + zg * (hprev - ng)) * keep;
            if (e2) hp1 = hn; else hp0 = hn;

            int j = j0 + u;
            hf hhi = __float2half_rn(hn);
            hf hlo = __float2half_rn(hn - __half2float(hhi));
            houtH[b*Hh + j] = hhi;
            houtL[b*Hh + j] = hlo;
            size_t hx = ((size_t)t * Bb + b) * Hh + j;
            g_hsh[hx] = hhi;
            g_hsl[hx] = hlo;
            hs[((size_t)t * Bb + b) * 2048 + j] = hn;
        }

        if (t < Ss - 1) {
            __syncthreads();
            if (tid == 0) {
                __threadfence();
                atomicAdd(&g_count, 1u);
                unsigned target = (unsigned)(t + 1) * SCAN_BLOCKS;
                while (atomicAdd(&g_count, 0u) < target)
                    __nanosleep(32);
                __threadfence();
            }
            __syncthreads();
        }
    }
}

__global__ void init_h_kernel(const float* __restrict__ h_init) {
    int idx = blockIdx.x * blockDim.x + threadIdx.x;
    float v = h_init[idx & (Hh - 1)];
    hf hi = __float2half_rn(v);
    g_ch_h[0][idx] = hi;
    g_ch_l[0][idx] = __float2half_rn(v - __half2float(hi));
    if (idx == 0) g_count = 0;
}

__global__ void softmax_kernel(float* __restrict__ attn,
                               const int* __restrict__ post_length,
                               hf* __restrict__ ah, hf* __restrict__ al)
{
    extern __shared__ float smf[];
    int s = blockIdx.x;
    float* base = attn + (size_t)s * Ll * Bb;
    for (int i = threadIdx.x; i < Ll * Bb; i += 256) {
        int l = i >> 6, b = i & 63;
        smf[b * 260 + l] = base[i];
    }
    __syncthreads();
    {
        int b = threadIdx.x >> 2, q = threadIdx.x & 3;
        int plen = post_length[b];
        float* row = smf + b * 260;
        float m = -INFINITY;
        for (int l = q; l < plen; l += 4) m = fmaxf(m, row[l]);
        m = fmaxf(m, __shfl_xor_sync(0xffffffff, m, 1));
        m = fmaxf(m, __shfl_xor_sync(0xffffffff, m, 2));
        float sum = 0.f;
        for (int l = q; l < plen; l += 4) {
            float e = expf(row[l] - m);
            row[l] = e;
            sum += e;
        }
        sum += __shfl_xor_sync(0xffffffff, sum, 1);
        sum += __shfl_xor_sync(0xffffffff, sum, 2);
        float inv = 1.f / sum;
        for (int l = q; l < plen; l += 4) row[l] *= inv;
        for (int l = plen + q; l < Ll; l += 4) row[l] = 0.f;
    }
    __syncthreads();
    for (int i = threadIdx.x; i < Ll * Bb; i += 256) {
        int l = i >> 6, b = i & 63;
        base[i] = smf[b * 260 + l];
    }
    for (int i = threadIdx.x; i < Ll * Bb; i += 256) {
        int b = i >> 8, l = i & 255;
        float v = smf[b * 260 + l];
        hf hi = __float2half_rn(v);
        size_t off = (size_t)b * (Ss * Ll) + (size_t)s * Ll + l;
        ah[off] = hi;
        al[off] = __float2half_rn(v - __half2float(hi));
    }
}

__global__ void copy_hlast_kernel(const float* __restrict__ hs, float* __restrict__ out) {
    int idx = blockIdx.x * blockDim.x + threadIdx.x;
    int b = idx >> 10, j = idx & 1023;
    out[idx] = hs[((size_t)255 * Bb + b) * 2048 + j];
}

extern "C" void kernel_launch(void* const* d_in, const int* in_sizes, int n_in,
                              void* d_out, int out_size)
{
    (void)in_sizes; (void)n_in; (void)out_size;
    const float* incoming = (const float*)d_in[0];
    const float* post     = (const float*)d_in[1];
    const float* h_init   = (const float*)d_in[2];
    const float* W_ih     = (const float*)d_in[3];
    const float* W_hh     = (const float*)d_in[4];
    const float* b_ih     = (const float*)d_in[5];
    const float* b_hh     = (const float*)d_in[6];
    const float* Wq       = (const float*)d_in[7];
    const float* bq       = (const float*)d_in[8];
    const int*   length   = (const int*)d_in[9];
    const int*   plen     = (const int*)d_in[10];

    float* out    = (float*)d_out;
    float* h_last = out;
    float* hs     = out + (size_t)Bb * Hh;
    float* attn   = hs + (size_t)Ss * Bb * 2048;

    float *GI;
    hf *inch, *incl, *Wih, *WhhH, *WhhL, *WqH, *WqL;
    hf *Qh, *Ql, *ph, *pl, *ah, *al, *hsH, *hsL;
    cudaGetSymbolAddress((void**)&GI,   g_GI);
    cudaGetSymbolAddress((void**)&inch, g_inch);
    cudaGetSymbolAddress((void**)&incl, g_incl);
    cudaGetSymbolAddress((void**)&Wih,  g_Wih);
    cudaGetSymbolAddress((void**)&WhhH, g_Whh_h);
    cudaGetSymbolAddress((void**)&WhhL, g_Whh_l);
    cudaGetSymbolAddress((void**)&WqH,  g_Wq_h);
    cudaGetSymbolAddress((void**)&WqL,  g_Wq_l);
    cudaGetSymbolAddress((void**)&Qh,   g_Qh);
    cudaGetSymbolAddress((void**)&Ql,   g_Ql);
    cudaGetSymbolAddress((void**)&ph,   g_ph);
    cudaGetSymbolAddress((void**)&pl,   g_pl);
    cudaGetSymbolAddress((void**)&ah,   g_ah);
    cudaGetSymbolAddress((void**)&al,   g_al);
    cudaGetSymbolAddress((void**)&hsH,  g_hsh);
    cudaGetSymbolAddress((void**)&hsL,  g_hsl);

    const int NT_SMEM   = 4 * 4 * 128 * 40 * (int)sizeof(hf);           // 163840
    const int NN_SMEM   = 2 * (2*128*40 + 2*32*136) * (int)sizeof(hf);  // 75776
    const int SCAN_SMEM = (2*32*1032 + 4*2*64*72) * (int)sizeof(hf);    // 205824
    const int SFT_SMEM  = 64 * 260 * (int)sizeof(float);                // 66560
    cudaFuncSetAttribute(wmma_split_nt,
                         cudaFuncAttributeMaxDynamicSharedMemorySize, NT_SMEM);
    cudaFuncSetAttribute(wmma_split_nn,
                         cudaFuncAttributeMaxDynamicSharedMemorySize, NN_SMEM);
    cudaFuncSetAttribute(gru_scan,
                         cudaFuncAttributeMaxDynamicSharedMemorySize, SCAN_SMEM);
    cudaFuncSetAttribute(softmax_kernel,
                         cudaFuncAttributeMaxDynamicSharedMemorySize, SFT_SMEM);

    init_h_kernel<<<256, 256>>>(h_init);
    split2_kernel<<<(Ss*Bb*Ii + 255)/256, 256>>>(incoming, inch, incl, Ss*Bb*Ii);
    tofp16_kernel<<<(H3*Ii + 255)/256, 256>>>(W_ih, Wih, H3*Ii);
    split2_kernel<<<(H3*Hh + 255)/256, 256>>>(W_hh, WhhH, WhhL, H3*Hh);
    split2_kernel<<<(Pp*Hh + 255)/256, 256>>>(Wq, WqH, WqL, Pp*Hh);

    // GI = incoming @ W_ih^T  (2-pass: the one reduced-precision source)
    wmma_split_nt<<<dim3(Ss*Bb/128, H3/128, 1), 256, NT_SMEM>>>(
        inch, incl, Ii, 0,  Wih, nullptr, Ii, 0,
        GI, H3, 1, 0,  nullptr, nullptr, nullptr,  Ii);

    split2_kernel<<<(Ll*Bb*Pp + 255)/256, 256>>>(post, ph, pl, Ll*Bb*Pp);

    gru_scan<<<SCAN_BLOCKS, 256, SCAN_SMEM>>>(b_ih, b_hh, length, h_init, hs);

    // Q = h_hist @ Wq^T + bq -> split (3-pass, fused epilogue)
    wmma_split_nt<<<dim3(Ss*Bb/128, Pp/128, 1), 256, NT_SMEM>>>(
        hsH, hsL, Hh, 0,  WqH, WqL, Hh, 0,
        nullptr, Pp, 1, 0,  bq, Qh, Ql,  Hh);

    // scores[s,l,b] = Q_b[s,:] . post_b[l,:]  (3-pass)
    wmma_split_nt<<<dim3(Ss/128, Ll/128, Bb), 256, NT_SMEM>>>(
        Qh, Ql, (long)Bb*Pp, Pp,  ph, pl, (long)Bb*Pp, Pp,
        attn, (long)Ll*Bb, Bb, 1,  nullptr, nullptr, nullptr,  Pp);

    softmax_kernel<<<Ss, 256, SFT_SMEM>>>(attn, plen, ah, al);

    // context = attn @ post (3-pass) -> hs[:, :, H:2H]
    wmma_split_nn<<<dim3(Ss/128, Pp/128, Bb), 256, NN_SMEM>>>(
        ah, al, Ll, (long)Ss*Ll,
        ph, pl, (long)Bb*Pp, Pp,
        hs + Hh, (long)Bb*2048, 2048,  Ll);

    copy_hlast_kernel<<<256, 256>>>(hs, h_last);
}

// round 16
// speedup vs baseline: 1.2831x; 1.0603x over previous
#include <cuda_runtime.h>
#include <cuda_fp16.h>
#include <mma.h>
#include <math.h>

using namespace nvcuda;
typedef __half hf;

#define Ss 256
#define Bb 64
#define Ii 1024
#define Hh 1024
#define H3 3072
#define Pp 1024
#define Ll 256
#define SCAN_BLOCKS 128

__device__ float g_GI[(size_t)Ss * Bb * H3];
__device__ hf g_inch[(size_t)Ss * Bb * Ii], g_incl[(size_t)Ss * Bb * Ii];
__device__ hf g_Wih[(size_t)H3 * Ii];                       // single fp16 (2-pass GI)
__device__ hf g_Whh_h[(size_t)H3 * Hh], g_Whh_l[(size_t)H3 * Hh];
__device__ hf g_Wq_h [(size_t)Pp * Hh], g_Wq_l [(size_t)Pp * Hh];
__device__ hf g_Qh[(size_t)Ss * Bb * Pp], g_Ql[(size_t)Ss * Bb * Pp];
__device__ hf g_ph[(size_t)Ll * Bb * Pp], g_pl[(size_t)Ll * Bb * Pp];
__device__ hf g_ah[(size_t)Bb * Ss * Ll], g_al[(size_t)Bb * Ss * Ll];
__device__ hf g_ch_h[2][Bb * Hh], g_ch_l[2][Bb * Hh];
__device__ unsigned g_count;

__device__ __forceinline__ void cpasync16(void* dst, const void* src) {
    unsigned d = (unsigned)__cvta_generic_to_shared(dst);
    asm volatile("cp.async.cg.shared.global [%0], [%1], 16;\n" :: "r"(d), "l"(src));
}
__device__ __forceinline__ void cpcommit() { asm volatile("cp.async.commit_group;\n"); }
template<int N> __device__ __forceinline__ void cpwait() {
    asm volatile("cp.async.wait_group %0;\n" :: "n"(N));
}
__device__ __forceinline__ void l2prefetch(const void* p) {
    asm volatile("prefetch.global.L2 [%0];" :: "l"(p));
}

__global__ void split2_kernel(const float* __restrict__ x,
                              hf* __restrict__ hi, hf* __restrict__ lo, int n)
{
    int i = blockIdx.x * blockDim.x + threadIdx.x;
    if (i < n) {
        float v = x[i];
        hf h = __float2half_rn(v);
        hi[i] = h;
        lo[i] = __float2half_rn(v - __half2float(h));
    }
}
__global__ void tofp16_kernel(const float* __restrict__ x, hf* __restrict__ y, int n)
{
    int i = blockIdx.x * blockDim.x + threadIdx.x;
    if (i < n) y[i] = __float2half_rn(x[i]);
}

// ---- fp16 NT GEMM: C = (Ah+Al) * (Bh[+Bl])^T; 3-pass if Bl, else 2-pass ----
__global__ void __launch_bounds__(256)
wmma_split_nt(const hf* __restrict__ Ah, const hf* __restrict__ Al,
              long ldaR, long batchA,
              const hf* __restrict__ Bh, const hf* __restrict__ Bl,
              long ldbR, long batchB,
              float* __restrict__ C, long ldcR, long cstr, long batchC,
              int K)
{
    extern __shared__ hf sm[];
    const int LD = 40;
    const int STG = 4 * 128 * LD;
    int z = blockIdx.z;
    Ah += (size_t)z * batchA;  Al += (size_t)z * batchA;
    Bh += (size_t)z * batchB;  if (Bl) Bl += (size_t)z * batchB;
    C += (size_t)z * batchC;
    int m0 = blockIdx.x * 128, n0 = blockIdx.y * 128;
    int tid = threadIdx.x;
    int w = tid >> 5, wr = w >> 2, wc = w & 3;
    bool has3 = (Bl != nullptr);

    wmma::fragment<wmma::accumulator,16,16,16,float> acc[4][2];
#pragma unroll
    for (int i = 0; i < 4; i++)
#pragma unroll
        for (int j = 0; j < 2; j++) wmma::fill_fragment(acc[i][j], 0.f);

    auto issue = [&](int kt) {
        hf* base = sm + (size_t)(kt & 3) * STG;
        int k0 = kt * 32;
#pragma unroll
        for (int i = 0; i < 8; i++) {
            int id = tid + 256 * i;
            int buf = id >> 9;
            if (buf == 3 && !has3) continue;
            int e = id & 511;
            int r = e >> 2, c = (e & 3) * 8;
            const hf* src;
            if      (buf == 0) src = Ah + (size_t)(m0 + r) * ldaR + k0 + c;
            else if (buf == 1) src = Al + (size_t)(m0 + r) * ldaR + k0 + c;
            else if (buf == 2) src = Bh + (size_t)(n0 + r) * ldbR + k0 + c;
            else               src = Bl + (size_t)(n0 + r) * ldbR + k0 + c;
            cpasync16(base + (size_t)buf * 128 * LD + r * LD + c, src);
        }
        cpcommit();
    };

    int KT = K / 32;
    issue(0); if (KT > 1) issue(1); if (KT > 2) issue(2);
    for (int kt = 0; kt < KT; kt++) {
        if      (kt < KT - 2)  cpwait<2>();
        else if (kt == KT - 2) cpwait<1>();
        else                   cpwait<0>();
        __syncthreads();
        if (kt + 3 < KT) issue(kt + 3);
        hf* base = sm + (size_t)(kt & 3) * STG;
        hf *sAh_ = base, *sAl_ = base + 128*LD, *sBh_ = base + 2*128*LD, *sBl_ = base + 3*128*LD;
#pragma unroll
        for (int ks = 0; ks < 2; ks++) {
            wmma::fragment<wmma::matrix_a,16,16,16,hf,wmma::row_major> ah[4], al[4];
            wmma::fragment<wmma::matrix_b,16,16,16,hf,wmma::col_major> bh[2], bl[2];
#pragma unroll
            for (int i = 0; i < 4; i++) {
                wmma::load_matrix_sync(ah[i], sAh_ + (wr*64 + i*16)*LD + ks*16, LD);
                wmma::load_matrix_sync(al[i], sAl_ + (wr*64 + i*16)*LD + ks*16, LD);
            }
#pragma unroll
            for (int j = 0; j < 2; j++) {
                wmma::load_matrix_sync(bh[j], sBh_ + (wc*32 + j*16)*LD + ks*16, LD);
                if (has3)
                    wmma::load_matrix_sync(bl[j], sBl_ + (wc*32 + j*16)*LD + ks*16, LD);
            }
#pragma unroll
            for (int i = 0; i < 4; i++)
#pragma unroll
                for (int j = 0; j < 2; j++) {
                    wmma::mma_sync(acc[i][j], ah[i], bh[j], acc[i][j]);
                    wmma::mma_sync(acc[i][j], al[i], bh[j], acc[i][j]);
                    if (has3)
                        wmma::mma_sync(acc[i][j], ah[i], bl[j], acc[i][j]);
                }
        }
    }
    __syncthreads();

    if (cstr == 1) {
#pragma unroll
        for (int i = 0; i < 4; i++)
#pragma unroll
            for (int j = 0; j < 2; j++)
                wmma::store_matrix_sync(
                    C + (size_t)(m0 + wr*64 + i*16) * ldcR + n0 + wc*32 + j*16,
                    acc[i][j], ldcR, wmma::mem_row_major);
    } else {
        float* smf = (float*)sm;
#pragma unroll
        for (int i = 0; i < 4; i++)
#pragma unroll
            for (int j = 0; j < 2; j++)
                wmma::store_matrix_sync(smf + (wr*64 + i*16)*128 + wc*32 + j*16,
                                        acc[i][j], 128, wmma::mem_row_major);
        __syncthreads();
        for (int e = tid; e < 16384; e += 256) {
            int m = e >> 7, n = e & 127;
            C[(size_t)(m0 + m) * ldcR + (size_t)(n0 + n) * cstr] = smf[e];
        }
    }
}

// ---- fp16 3-pass NN GEMM (context) ----
__global__ void __launch_bounds__(256)
wmma_split_nn(const hf* __restrict__ Ah, const hf* __restrict__ Al,
              long ldaR, long batchA,
              const hf* __restrict__ Bh, const hf* __restrict__ Bl,
              long ldbR, long batchB,
              float* __restrict__ C, long ldcR, long batchC, int K)
{
    extern __shared__ hf sm[];
    const int ALD = 40, BLD = 136;
    const int STG = 2*128*ALD + 2*32*BLD;
    int z = blockIdx.z;
    Ah += (size_t)z * batchA;  Al += (size_t)z * batchA;
    Bh += (size_t)z * batchB;  Bl += (size_t)z * batchB;
    C  += (size_t)z * batchC;
    int m0 = blockIdx.x * 128, n0 = blockIdx.y * 128;
    int tid = threadIdx.x;
    int w = tid >> 5, wr = w >> 2, wc = w & 3;

    wmma::fragment<wmma::accumulator,16,16,16,float> acc[4][2];
#pragma unroll
    for (int i = 0; i < 4; i++)
#pragma unroll
        for (int j = 0; j < 2; j++) wmma::fill_fragment(acc[i][j], 0.f);

    auto issue = [&](int kt, int stg) {
        hf* base = sm + (size_t)stg * STG;
        hf *dAh = base, *dAl = base + 128*ALD, *dBh = base + 2*128*ALD, *dBl = base + 2*128*ALD + 32*BLD;
        int k0 = kt * 32;
#pragma unroll
        for (int i = 0; i < 8; i++) {
            int id = tid + 256 * i;
            int buf = id >> 9;
            int e = id & 511;
            if (buf < 2) {
                int r = e >> 2, c = (e & 3) * 8;
                const hf* src = (buf ? Al : Ah) + (size_t)(m0 + r) * ldaR + k0 + c;
                cpasync16((buf ? dAl : dAh) + r * ALD + c, src);
            } else {
                int r = e >> 4, c = (e & 15) * 8;
                const hf* src = (buf == 3 ? Bl : Bh) + (size_t)(k0 + r) * ldbR + n0 + c;
                cpasync16((buf == 3 ? dBl : dBh) + r * BLD + c, src);
            }
        }
        cpcommit();
    };

    int KT = K / 32;
    issue(0, 0);
    for (int kt = 0; kt < KT; kt++) {
        if (kt + 1 < KT) { issue(kt + 1, (kt + 1) & 1); cpwait<1>(); }
        else             { cpwait<0>(); }
        __syncthreads();
        hf* base = sm + (size_t)(kt & 1) * STG;
        hf *sAh_ = base, *sAl_ = base + 128*ALD, *sBh_ = base + 2*128*ALD, *sBl_ = sBh_ + 32*BLD;
#pragma unroll
        for (int ks = 0; ks < 2; ks++) {
            wmma::fragment<wmma::matrix_a,16,16,16,hf,wmma::row_major> ah[4], al[4];
            wmma::fragment<wmma::matrix_b,16,16,16,hf,wmma::row_major> bh[2], bl[2];
#pragma unroll
            for (int i = 0; i < 4; i++) {
                wmma::load_matrix_sync(ah[i], sAh_ + (wr*64 + i*16)*ALD + ks*16, ALD);
                wmma::load_matrix_sync(al[i], sAl_ + (wr*64 + i*16)*ALD + ks*16, ALD);
            }
#pragma unroll
            for (int j = 0; j < 2; j++) {
                wmma::load_matrix_sync(bh[j], sBh_ + (ks*16)*BLD + wc*32 + j*16, BLD);
                wmma::load_matrix_sync(bl[j], sBl_ + (ks*16)*BLD + wc*32 + j*16, BLD);
            }
#pragma unroll
            for (int i = 0; i < 4; i++)
#pragma unroll
                for (int j = 0; j < 2; j++) {
                    wmma::mma_sync(acc[i][j], ah[i], bh[j], acc[i][j]);
                    wmma::mma_sync(acc[i][j], ah[i], bl[j], acc[i][j]);
                    wmma::mma_sync(acc[i][j], al[i], bh[j], acc[i][j]);
                }
        }
        __syncthreads();
    }
#pragma unroll
    for (int i = 0; i < 4; i++)
#pragma unroll
        for (int j = 0; j < 2; j++)
            wmma::store_matrix_sync(
                C + (size_t)(m0 + wr*64 + i*16) * ldcR + n0 + wc*32 + j*16,
                acc[i][j], ldcR, wmma::mem_row_major);
}

// ---- persistent GRU scan + FUSED Q: B tile = [24 W_hh rows | 8 Wq rows] ----
// acc cols 0-23 = gh, cols 24-31 = Q[t-1]. Extra iteration t==Ss emits Q[255].
__global__ void __launch_bounds__(256)
gru_scan(const float* __restrict__ bih, const float* __restrict__ bhh,
         const float* __restrict__ bq,
         const int* __restrict__ length, const float* __restrict__ h_init,
         float* __restrict__ hs)
{
    extern __shared__ hf ssm[];
    const int WLD = 1032, ALD = 72;
    const int ASTG = 2 * 64 * ALD;
    hf* sWh = ssm;
    hf* sWl = sWh + 32 * WLD;
    hf* sA  = sWl + 32 * WLD;
    float* ghsm = (float*)sA;

    int tid = threadIdx.x;
    int w = tid >> 5, wr = w & 3, wc = w >> 2;
    int j0 = blockIdx.x * 8;

    for (int i = tid; i < 32 * WLD; i += 256) {
        sWh[i] = __float2half_rn(0.f);
        sWl[i] = __float2half_rn(0.f);
    }
    __syncthreads();
    // rows 0-23: W_hh gates; rows 24-31: Wq rows for this CTA's 8 Q-columns
    for (int i = tid; i < 32 * 128; i += 256) {
        int rb = i >> 7, c = (i & 127) * 8;
        const hf *srcH, *srcL;
        if (rb < 24) {
            size_t wrow = (size_t)((rb >> 3) * 1024 + j0 + (rb & 7));
            srcH = g_Whh_h + wrow * Hh;  srcL = g_Whh_l + wrow * Hh;
        } else {
            size_t qrow = (size_t)(j0 + (rb - 24));
            srcH = g_Wq_h + qrow * Hh;   srcL = g_Wq_l + qrow * Hh;
        }
        *(uint4*)(sWh + rb * WLD + c) = *(const uint4*)(srcH + c);
        *(uint4*)(sWl + rb * WLD + c) = *(const uint4*)(srcL + c);
    }

    int u = tid & 7, bA = tid >> 3;
    float hp0 = h_init[j0 + u], hp1 = hp0;
    int len0 = length[bA], len1 = length[bA + 32];
    float br = bhh[j0+u], bz = bhh[Hh+j0+u], bn = bhh[2*Hh+j0+u];
    float cr = bih[j0+u], cz = bih[Hh+j0+u], cn = bih[2*Hh+j0+u];
    float bqv = bq[j0 + u];
    __syncthreads();

    for (int t = 0; t <= Ss; t++) {
        const hf* hinH = &g_ch_h[t & 1][0];
        const hf* hinL = &g_ch_l[t & 1][0];
        hf* houtH = &g_ch_h[(t + 1) & 1][0];
        hf* houtL = &g_ch_l[(t + 1) & 1][0];

        // prefetch this step's GI operands into L2 (consumed after the MMA loop)
        if (t < Ss) {
            const float* GIp = g_GI + ((size_t)t * Bb + bA) * H3 + j0 + u;
#pragma unroll
            for (int e2 = 0; e2 < 2; e2++) {
                const float* p = GIp + (size_t)e2 * 32 * H3;
                l2prefetch(p); l2prefetch(p + Hh); l2prefetch(p + 2*Hh);
            }
        }

        wmma::fragment<wmma::accumulator,16,16,16,float> acc0, acc1, acc2;
        wmma::fill_fragment(acc0, 0.f);
        wmma::fill_fragment(acc1, 0.f);
        wmma::fill_fragment(acc2, 0.f);

        auto issueA = [&](int kc, int stg) {
            hf* dh = sA + (size_t)stg * ASTG;
            hf* dl = dh + 64 * ALD;
#pragma unroll
            for (int i = 0; i < 4; i++) {
                int id = tid + 256 * i;
                int half_ = id >> 9;
                int e = id & 511;
                int r = e >> 3, c = (e & 7) * 8;
                const hf* src = (half_ ? hinL : hinH) + r * Hh + kc * 64 + c;
                cpasync16((half_ ? dl : dh) + r * ALD + c, src);
            }
            cpcommit();
        };

        issueA(0, 0); issueA(1, 1); issueA(2, 2);
        for (int kc = 0; kc < 16; kc++) {
            if      (kc <= 13) cpwait<2>();
            else if (kc == 14) cpwait<1>();
            else               cpwait<0>();
            __syncthreads();
            if (kc + 3 < 16) issueA(kc + 3, (kc + 3) & 3);
            hf* dh = sA + (size_t)(kc & 3) * ASTG;
            hf* dl = dh + 64 * ALD;
#pragma unroll
            for (int ks = 0; ks < 4; ks++) {
                wmma::fragment<wmma::matrix_a,16,16,16,hf,wmma::row_major> ah, al;
                wmma::fragment<wmma::matrix_b,16,16,16,hf,wmma::col_major> bhf, blf;
                wmma::load_matrix_sync(ah, dh + (wr*16)*ALD + ks*16, ALD);
                wmma::load_matrix_sync(al, dl + (wr*16)*ALD + ks*16, ALD);
                wmma::load_matrix_sync(bhf, sWh + (wc*16)*WLD + kc*64 + ks*16, WLD);
                wmma::load_matrix_sync(blf, sWl + (wc*16)*WLD + kc*64 + ks*16, WLD);
                wmma::mma_sync(acc0, ah, bhf, acc0);
                wmma::mma_sync(acc1, ah, blf, acc1);
                wmma::mma_sync(acc2, al, bhf, acc2);
            }
        }
#pragma unroll
        for (int i = 0; i < acc0.num_elements; i++)
            acc0.x[i] += acc1.x[i] + acc2.x[i];
        __syncthreads();
        wmma::store_matrix_sync(ghsm + (wr*16)*36 + wc*16, acc0, 36, wmma::mem_row_major);
        __syncthreads();

#pragma unroll
        for (int e2 = 0; e2 < 2; e2++) {
            int b = bA + e2 * 32;
            // Q[t-1] from acc cols 24-31 (valid for t >= 1)
            if (t >= 1) {
                float qv = ghsm[b*36 + 24 + u] + bqv;
                hf qhi = __float2half_rn(qv);
                size_t qoff = ((size_t)(t - 1) * Bb + b) * Pp + j0 + u;
                g_Qh[qoff] = qhi;
                g_Ql[qoff] = __float2half_rn(qv - __half2float(qhi));
            }
            if (t < Ss) {
                float hprev = e2 ? hp1 : hp0;
                int   len   = e2 ? len1 : len0;
                float ghr = ghsm[b*36 + u]      + br;
                float ghz = ghsm[b*36 + 8 + u]  + bz;
                float ghn = ghsm[b*36 + 16 + u] + bn;
                const float* GIt = g_GI + ((size_t)t * Bb + b) * H3 + j0 + u;
                float gir = GIt[0]     + cr;
                float giz = GIt[Hh]    + cz;
                float gin = GIt[2*Hh]  + cn;
                float rg = 1.f / (1.f + expf(-(gir + ghr)));
                float zg = 1.f / (1.f + expf(-(giz + ghz)));
                float ng = tanhf(gin + rg * ghn);
                float keep = (t < len) ? 1.f : 0.f;
                float hn = (ng + zg * (hprev - ng)) * keep;
                if (e2) hp1 = hn; else hp0 = hn;

                int j = j0 + u;
                hf hhi = __float2half_rn(hn);
                hf hlo = __float2half_rn(hn - __half2float(hhi));
                houtH[b*Hh + j] = hhi;
                houtL[b*Hh + j] = hlo;
                hs[((size_t)t * Bb + b) * 2048 + j] = hn;
            }
        }

        if (t < Ss) {
            __syncthreads();
            if (tid == 0) {
                __threadfence();
                atomicAdd(&g_count, 1u);
                unsigned target = (unsigned)(t + 1) * SCAN_BLOCKS;
                while (atomicAdd(&g_count, 0u) < target)
                    __nanosleep(32);
                __threadfence();
            }
            __syncthreads();
        }
    }
}

__global__ void init_h_kernel(const float* __restrict__ h_init) {
    int idx = blockIdx.x * blockDim.x + threadIdx.x;
    float v = h_init[idx & (Hh - 1)];
    hf hi = __float2half_rn(v);
    g_ch_h[0][idx] = hi;
    g_ch_l[0][idx] = __float2half_rn(v - __half2float(hi));
    if (idx == 0) g_count = 0;
}

__global__ void softmax_kernel(float* __restrict__ attn,
                               const int* __restrict__ post_length,
                               hf* __restrict__ ah, hf* __restrict__ al)
{
    extern __shared__ float smf[];
    int s = blockIdx.x;
    float* base = attn + (size_t)s * Ll * Bb;
    for (int i = threadIdx.x; i < Ll * Bb; i += 256) {
        int l = i >> 6, b = i & 63;
        smf[b * 260 + l] = base[i];
    }
    __syncthreads();
    {
        int b = threadIdx.x >> 2, q = threadIdx.x & 3;
        int plen = post_length[b];
        float* row = smf + b * 260;
        float m = -INFINITY;
        for (int l = q; l < plen; l += 4) m = fmaxf(m, row[l]);
        m = fmaxf(m, __shfl_xor_sync(0xffffffff, m, 1));
        m = fmaxf(m, __shfl_xor_sync(0xffffffff, m, 2));
        float sum = 0.f;
        for (int l = q; l < plen; l += 4) {
            float e = expf(row[l] - m);
            row[l] = e;
            sum += e;
        }
        sum += __shfl_xor_sync(0xffffffff, sum, 1);
        sum += __shfl_xor_sync(0xffffffff, sum, 2);
        float inv = 1.f / sum;
        for (int l = q; l < plen; l += 4) row[l] *= inv;
        for (int l = plen + q; l < Ll; l += 4) row[l] = 0.f;
    }
    __syncthreads();
    for (int i = threadIdx.x; i < Ll * Bb; i += 256) {
        int l = i >> 6, b = i & 63;
        base[i] = smf[b * 260 + l];
    }
    for (int i = threadIdx.x; i < Ll * Bb; i += 256) {
        int b = i >> 8, l = i & 255;
        float v = smf[b * 260 + l];
        hf hi = __float2half_rn(v);
        size_t off = (size_t)b * (Ss * Ll) + (size_t)s * Ll + l;
        ah[off] = hi;
        al[off] = __float2half_rn(v - __half2float(hi));
    }
}

__global__ void copy_hlast_kernel(const float* __restrict__ hs, float* __restrict__ out) {
    int idx = blockIdx.x * blockDim.x + threadIdx.x;
    int b = idx >> 10, j = idx & 1023;
    out[idx] = hs[((size_t)255 * Bb + b) * 2048 + j];
}

extern "C" void kernel_launch(void* const* d_in, const int* in_sizes, int n_in,
                              void* d_out, int out_size)
{
    (void)in_sizes; (void)n_in; (void)out_size;
    const float* incoming = (const float*)d_in[0];
    const float* post     = (const float*)d_in[1];
    const float* h_init   = (const float*)d_in[2];
    const float* W_ih     = (const float*)d_in[3];
    const float* W_hh     = (const float*)d_in[4];
    const float* b_ih     = (const float*)d_in[5];
    const float* b_hh     = (const float*)d_in[6];
    const float* Wq       = (const float*)d_in[7];
    const float* bq       = (const float*)d_in[8];
    const int*   length   = (const int*)d_in[9];
    const int*   plen     = (const int*)d_in[10];

    float* out    = (float*)d_out;
    float* h_last = out;
    float* hs     = out + (size_t)Bb * Hh;
    float* attn   = hs + (size_t)Ss * Bb * 2048;

    float *GI;
    hf *inch, *incl, *Wih, *WhhH, *WhhL, *WqH, *WqL;
    hf *Qh, *Ql, *ph, *pl, *ah, *al;
    cudaGetSymbolAddress((void**)&GI,   g_GI);
    cudaGetSymbolAddress((void**)&inch, g_inch);
    cudaGetSymbolAddress((void**)&incl, g_incl);
    cudaGetSymbolAddress((void**)&Wih,  g_Wih);
    cudaGetSymbolAddress((void**)&WhhH, g_Whh_h);
    cudaGetSymbolAddress((void**)&WhhL, g_Whh_l);
    cudaGetSymbolAddress((void**)&WqH,  g_Wq_h);
    cudaGetSymbolAddress((void**)&WqL,  g_Wq_l);
    cudaGetSymbolAddress((void**)&Qh,   g_Qh);
    cudaGetSymbolAddress((void**)&Ql,   g_Ql);
    cudaGetSymbolAddress((void**)&ph,   g_ph);
    cudaGetSymbolAddress((void**)&pl,   g_pl);
    cudaGetSymbolAddress((void**)&ah,   g_ah);
    cudaGetSymbolAddress((void**)&al,   g_al);

    const int NT_SMEM   = 4 * 4 * 128 * 40 * (int)sizeof(hf);           // 163840
    const int NN_SMEM   = 2 * (2*128*40 + 2*32*136) * (int)sizeof(hf);  // 75776
    const int SCAN_SMEM = (2*32*1032 + 4*2*64*72) * (int)sizeof(hf);    // 205824
    const int SFT_SMEM  = 64 * 260 * (int)sizeof(float);                // 66560
    cudaFuncSetAttribute(wmma_split_nt,
                         cudaFuncAttributeMaxDynamicSharedMemorySize, NT_SMEM);
    cudaFuncSetAttribute(wmma_split_nn,
                         cudaFuncAttributeMaxDynamicSharedMemorySize, NN_SMEM);
    cudaFuncSetAttribute(gru_scan,
                         cudaFuncAttributeMaxDynamicSharedMemorySize, SCAN_SMEM);
    cudaFuncSetAttribute(softmax_kernel,
                         cudaFuncAttributeMaxDynamicSharedMemorySize, SFT_SMEM);

    init_h_kernel<<<256, 256>>>(h_init);
    split2_kernel<<<(Ss*Bb*Ii + 255)/256, 256>>>(incoming, inch, incl, Ss*Bb*Ii);
    tofp16_kernel<<<(H3*Ii + 255)/256, 256>>>(W_ih, Wih, H3*Ii);
    split2_kernel<<<(H3*Hh + 255)/256, 256>>>(W_hh, WhhH, WhhL, H3*Hh);
    split2_kernel<<<(Pp*Hh + 255)/256, 256>>>(Wq, WqH, WqL, Pp*Hh);

    // GI = incoming @ W_ih^T  (2-pass)
    wmma_split_nt<<<dim3(Ss*Bb/128, H3/128, 1), 256, NT_SMEM>>>(
        inch, incl, Ii, 0,  Wih, nullptr, Ii, 0,
        GI, H3, 1, 0,  Ii);

    split2_kernel<<<(Ll*Bb*Pp + 255)/256, 256>>>(post, ph, pl, Ll*Bb*Pp);

    // persistent scan with fused Q (Ss+1 iterations)
    gru_scan<<<SCAN_BLOCKS, 256, SCAN_SMEM>>>(b_ih, b_hh, bq, length, h_init, hs);

    // scores[s,l,b] = Q_b[s,:] . post_b[l,:]  (3-pass)
    wmma_split_nt<<<dim3(Ss/128, Ll/128, Bb), 256, NT_SMEM>>>(
        Qh, Ql, (long)Bb*Pp, Pp,  ph, pl, (long)Bb*Pp, Pp,
        attn, (long)Ll*Bb, Bb, 1,  Pp);

    softmax_kernel<<<Ss, 256, SFT_SMEM>>>(attn, plen, ah, al);

    // context = attn @ post (3-pass) -> hs[:, :, H:2H]
    wmma_split_nn<<<dim3(Ss/128, Pp/128, Bb), 256, NN_SMEM>>>(
        ah, al, Ll, (long)Ss*Ll,
        ph, pl, (long)Bb*Pp, Pp,
        hs + Hh, (long)Bb*2048, 2048,  Ll);

    copy_hlast_kernel<<<256, 256>>>(hs, h_last);
}